// round 11
// baseline (speedup 1.0000x reference)
#include <cuda_runtime.h>
#include <cuda_fp16.h>
#include <math.h>
#include <stdint.h>

#define NN 100000
#define EE 1600000
#define NB_SCAN ((NN + 1023) / 1024)

// ---------------- scratch (static device globals) ----------------
__device__ float    g_deg[NN];
__device__ float    g_dinv[NN];
__device__ __half   g_xt1[(size_t)NN * 128];
__device__ float    g_al1[NN * 4];
__device__ float    g_ar1[NN * 4];
__device__ __half   g_h1[(size_t)NN * 128];
__device__ __half   g_xt2[NN * 16];
__device__ float    g_al2[NN];
__device__ float    g_ar2[NN];
// CSR by destination (col)
__device__ int      g_cnt[NN];
__device__ int      g_off[NN + 1];
__device__ int      g_wpos[NN];
__device__ int      g_bsum[NB_SCAN + 1];
__device__ int      g_adj[EE];     // source row only

__device__ __forceinline__ float lrelu(float a) { return a >= 0.f ? a : 0.2f * a; }

__device__ __forceinline__ float f2tf(float f) {
    uint32_t u;
    asm("cvt.rna.tf32.f32 %0, %1;" : "=r"(u) : "f"(f));
    return __uint_as_float(u);
}
__device__ __forceinline__ uint32_t f2tfu(float f) {
    uint32_t u;
    asm("cvt.rna.tf32.f32 %0, %1;" : "=r"(u) : "f"(f));
    return u;
}

__device__ __forceinline__ void mma_tf32(float* c, const uint32_t* a, const uint32_t* b) {
    asm volatile(
        "mma.sync.aligned.m16n8k8.row.col.f32.tf32.tf32.f32 "
        "{%0,%1,%2,%3}, {%4,%5,%6,%7}, {%8,%9}, {%0,%1,%2,%3};"
        : "+f"(c[0]), "+f"(c[1]), "+f"(c[2]), "+f"(c[3])
        : "r"(a[0]), "r"(a[1]), "r"(a[2]), "r"(a[3]), "r"(b[0]), "r"(b[1]));
}

__device__ __forceinline__ void cp16(uint32_t d, const void* s, int sz) {
    asm volatile("cp.async.ca.shared.global [%0], [%1], 16, %2;"
                 :: "r"(d), "l"(s), "r"(sz));
}
__device__ __forceinline__ void cp_commit() {
    asm volatile("cp.async.commit_group;" ::: "memory");
}

// ---------------- init ----------------
__global__ void k_init(int n) {
    int i = blockIdx.x * blockDim.x + threadIdx.x;
    if (i < n) { g_deg[i] = 1.0f; g_cnt[i] = 0; }
}

__global__ void k_deg_count(const int* __restrict__ ei, int e) {
    int i = blockIdx.x * blockDim.x + threadIdx.x;
    if (i < e) {
        atomicAdd(&g_deg[ei[i]], 1.0f);
        atomicAdd(&g_cnt[ei[e + i]], 1);
    }
}

// ---------------- multi-block exclusive scan over g_cnt (+ fused dinv) ----------------
__global__ void k_scan_blocks(int n) {
    __shared__ int warpsums[32];
    int i = blockIdx.x * 1024 + threadIdx.x;
    int lane = threadIdx.x & 31, wid = threadIdx.x >> 5;
    if (i < n) g_dinv[i] = rsqrtf(g_deg[i]);   // fused dinv
    int v = (i < n) ? g_cnt[i] : 0;
    int s = v;
#pragma unroll
    for (int d = 1; d < 32; d <<= 1) {
        int t = __shfl_up_sync(0xffffffffu, s, d);
        if (lane >= d) s += t;
    }
    if (lane == 31) warpsums[wid] = s;
    __syncthreads();
    if (wid == 0) {
        int ws = warpsums[lane];
#pragma unroll
        for (int d = 1; d < 32; d <<= 1) {
            int t = __shfl_up_sync(0xffffffffu, ws, d);
            if (lane >= d) ws += t;
        }
        warpsums[lane] = ws;
    }
    __syncthreads();
    int base = (wid > 0) ? warpsums[wid - 1] : 0;
    int exc = s - v + base;
    if (i < n) g_off[i] = exc;
    if (threadIdx.x == 1023) g_bsum[blockIdx.x] = exc + v;  // raw block total
}

// scan_add computes its own block base from raw totals
__global__ void k_scan_add(int n, int e) {
    __shared__ int sbase;
    if (threadIdx.x == 0) sbase = 0;
    __syncthreads();
    if (threadIdx.x < blockIdx.x) atomicAdd(&sbase, g_bsum[threadIdx.x]);
    __syncthreads();
    int i = blockIdx.x * 1024 + threadIdx.x;
    if (i < n) {
        int o = g_off[i] + sbase;
        g_off[i] = o;
        g_wpos[i] = o;
    }
    if (i == 0) g_off[n] = e;
}

__global__ void k_scatter(const int* __restrict__ ei, int e) {
    int i = blockIdx.x * blockDim.x + threadIdx.x;
    if (i >= e) return;
    int r = ei[i], c = ei[e + i];
    int p = atomicAdd(&g_wpos[c], 1);
    g_adj[p] = r;
}

// ---------------- GEMM1 (tf32, cp.async double-buffered, RNA cvt on fragments) ----------------
__global__ __launch_bounds__(256, 2) void k_gemm1(const float* __restrict__ X,
                                                  const float* __restrict__ W,
                                                  const float* __restrict__ att, int n) {
    __shared__ __align__(16) float Xs[2][128][20];   // [m][k] + pad4
    __shared__ __align__(16) float Ws[2][16][132];   // [k][n] + pad4
    int tid = threadIdx.x, lane = tid & 31, wid = tid >> 5;
    int m0 = blockIdx.x * 128;
    int wm = (wid & 1) * 64, wn = (wid >> 1) * 32;

    float acc[4][4][4];
#pragma unroll
    for (int mt = 0; mt < 4; mt++)
#pragma unroll
        for (int nt = 0; nt < 4; nt++)
#pragma unroll
            for (int q = 0; q < 4; q++) acc[mt][nt][q] = 0.f;

    int lm = tid & 127;
    int lkq = (tid >> 7) * 8;
    int wk = tid >> 4;
    int wq = (tid & 15) * 8;

    bool mok = (m0 + lm < n);
    int xsz = mok ? 16 : 0;
    const float* xsrc = X + (size_t)(m0 + lm) * 256 + lkq;
    const float* wsrc = W + (size_t)wk * 128 + wq;
    uint32_t xd = (uint32_t)__cvta_generic_to_shared(&Xs[0][lm][lkq]);
    uint32_t wd = (uint32_t)__cvta_generic_to_shared(&Ws[0][wk][wq]);
    const uint32_t XST = sizeof(float) * 128 * 20;
    const uint32_t WST = sizeof(float) * 16 * 132;

    cp16(xd, xsrc, xsz);
    cp16(xd + 16, xsrc + 4, xsz);
    cp16(wd, wsrc, 16);
    cp16(wd + 16, wsrc + 4, 16);
    cp_commit();

#pragma unroll 1
    for (int t = 0; t < 16; t++) {
        int s = t & 1;
        if (t + 1 < 16) {
            int s1 = (t + 1) & 1;
            int k0 = (t + 1) * 16;
            cp16(xd + s1 * XST, xsrc + k0, xsz);
            cp16(xd + s1 * XST + 16, xsrc + k0 + 4, xsz);
            cp16(wd + s1 * WST, wsrc + (size_t)k0 * 128, 16);
            cp16(wd + s1 * WST + 16, wsrc + (size_t)k0 * 128 + 4, 16);
            cp_commit();
            asm volatile("cp.async.wait_group 1;" ::: "memory");
        } else {
            asm volatile("cp.async.wait_group 0;" ::: "memory");
        }
        __syncthreads();

#pragma unroll
        for (int kk = 0; kk < 16; kk += 8) {
            int ar = lane >> 2, ak = kk + (lane & 3);
            uint32_t a[4][4], b[4][2];
#pragma unroll
            for (int mt = 0; mt < 4; mt++) {
                int r = wm + mt * 16 + ar;
                a[mt][0] = f2tfu(Xs[s][r][ak]);
                a[mt][1] = f2tfu(Xs[s][r + 8][ak]);
                a[mt][2] = f2tfu(Xs[s][r][ak + 4]);
                a[mt][3] = f2tfu(Xs[s][r + 8][ak + 4]);
            }
#pragma unroll
            for (int nt = 0; nt < 4; nt++) {
                int c = wn + nt * 8 + ar;
                b[nt][0] = f2tfu(Ws[s][ak][c]);
                b[nt][1] = f2tfu(Ws[s][ak + 4][c]);
            }
#pragma unroll
            for (int mt = 0; mt < 4; mt++)
#pragma unroll
                for (int nt = 0; nt < 4; nt++)
                    mma_tf32(acc[mt][nt], a[mt], b[nt]);
        }
        __syncthreads();
    }

    int ar = lane >> 2, ac = (lane & 3) * 2;
#pragma unroll
    for (int mt = 0; mt < 4; mt++) {
        int r = m0 + wm + mt * 16 + ar;
#pragma unroll
        for (int nt = 0; nt < 4; nt++) {
            int c = wn + nt * 8 + ac;
            if (r < n)
                *(__half2*)&g_xt1[(size_t)r * 128 + c] =
                    __floats2half2_rn(acc[mt][nt][0], acc[mt][nt][1]);
            if (r + 8 < n)
                *(__half2*)&g_xt1[(size_t)(r + 8) * 128 + c] =
                    __floats2half2_rn(acc[mt][nt][2], acc[mt][nt][3]);
        }
    }

    // ---- fused alar1 epilogue ----
    int hh = wid >> 1;
    float wlv[8], wrv[8];
#pragma unroll
    for (int nt = 0; nt < 4; nt++) {
        int cc = nt * 8 + ac;
        wlv[nt * 2 + 0] = att[hh * 64 + cc];
        wlv[nt * 2 + 1] = att[hh * 64 + cc + 1];
        wrv[nt * 2 + 0] = att[hh * 64 + 32 + cc];
        wrv[nt * 2 + 1] = att[hh * 64 + 32 + cc + 1];
    }
#pragma unroll
    for (int mt = 0; mt < 4; mt++) {
        float alp0 = 0.f, arp0 = 0.f, alp1 = 0.f, arp1 = 0.f;
#pragma unroll
        for (int nt = 0; nt < 4; nt++) {
            alp0 += acc[mt][nt][0] * wlv[nt * 2] + acc[mt][nt][1] * wlv[nt * 2 + 1];
            arp0 += acc[mt][nt][0] * wrv[nt * 2] + acc[mt][nt][1] * wrv[nt * 2 + 1];
            alp1 += acc[mt][nt][2] * wlv[nt * 2] + acc[mt][nt][3] * wlv[nt * 2 + 1];
            arp1 += acc[mt][nt][2] * wrv[nt * 2] + acc[mt][nt][3] * wrv[nt * 2 + 1];
        }
#pragma unroll
        for (int d = 1; d <= 2; d <<= 1) {
            alp0 += __shfl_xor_sync(0xffffffffu, alp0, d);
            arp0 += __shfl_xor_sync(0xffffffffu, arp0, d);
            alp1 += __shfl_xor_sync(0xffffffffu, alp1, d);
            arp1 += __shfl_xor_sync(0xffffffffu, arp1, d);
        }
        if ((lane & 3) == 0) {
            int r = m0 + wm + mt * 16 + ar;
            if (r < n)     { g_al1[r * 4 + hh] = alp0;       g_ar1[r * 4 + hh] = arp0; }
            if (r + 8 < n) { g_al1[(r + 8) * 4 + hh] = alp1; g_ar1[(r + 8) * 4 + hh] = arp1; }
        }
    }
}

// ---------------- agg1: warp per node, paired-edge half-warp gathers ----------------
__global__ void k_agg1(const float* __restrict__ b1, int n) {
    __shared__ float sw[8][32][4];
    __shared__ int   sr[8][32];
    int w = (blockIdx.x * blockDim.x + threadIdx.x) >> 5;
    if (w >= n) return;
    int lane = threadIdx.x & 31;
    int wz = (threadIdx.x >> 5) & 7;
    int c = w;
    int sub = lane & 15;       // channel group: 8 channels = sub*8..sub*8+7
    int pair = lane >> 4;      // edge parity
    int h = sub >> 2;          // head of this channel group (32 ch per head)
    float dc = g_dinv[c];
    float4 alc = *(const float4*)&g_al1[c * 4];
    float4 arc = *(const float4*)&g_ar1[c * 4];
    int beg = g_off[c], end = g_off[c + 1];

    float4 ps = make_float4(0.f, 0.f, 0.f, 0.f);
    float acc[8];
#pragma unroll
    for (int i = 0; i < 8; i++) acc[i] = 0.f;

    for (int t0 = beg; t0 < end; t0 += 32) {
        int j = t0 + lane;
        if (j < end) {
            int r = __ldg(&g_adj[j]);
            float4 ar4 = *(const float4*)&g_ar1[r * 4];
            float di = g_dinv[r];
            float e0 = __expf(lrelu(alc.x + ar4.x));
            float e1 = __expf(lrelu(alc.y + ar4.y));
            float e2 = __expf(lrelu(alc.z + ar4.z));
            float e3 = __expf(lrelu(alc.w + ar4.w));
            ps.x += e0; ps.y += e1; ps.z += e2; ps.w += e3;
            sw[wz][lane][0] = di * e0;
            sw[wz][lane][1] = di * e1;
            sw[wz][lane][2] = di * e2;
            sw[wz][lane][3] = di * e3;
            sr[wz][lane] = r;
        }
        __syncwarp();
        int cnt = min(32, end - t0);
        // two edges in flight: half-warp `pair` handles edges u = pair, pair+2, ...
#pragma unroll 4
        for (int u = pair; u < cnt; u += 2) {
            int r = sr[wz][u];
            float wh = sw[wz][u][h];
            uint4 v = *(const uint4*)&g_xt1[(size_t)r * 128 + sub * 8];
            float2 f0 = __half22float2(*(__half2*)&v.x);
            float2 f1 = __half22float2(*(__half2*)&v.y);
            float2 f2 = __half22float2(*(__half2*)&v.z);
            float2 f3 = __half22float2(*(__half2*)&v.w);
            acc[0] += wh * f0.x; acc[1] += wh * f0.y;
            acc[2] += wh * f1.x; acc[3] += wh * f1.y;
            acc[4] += wh * f2.x; acc[5] += wh * f2.y;
            acc[6] += wh * f3.x; acc[7] += wh * f3.y;
        }
        __syncwarp();
    }

    // softmax denominator (full-warp reduce)
#pragma unroll
    for (int d = 16; d > 0; d >>= 1) {
        ps.x += __shfl_xor_sync(0xffffffffu, ps.x, d);
        ps.y += __shfl_xor_sync(0xffffffffu, ps.y, d);
        ps.z += __shfl_xor_sync(0xffffffffu, ps.z, d);
        ps.w += __shfl_xor_sync(0xffffffffu, ps.w, d);
    }
    float se0 = __expf(lrelu(alc.x + arc.x));
    float se1 = __expf(lrelu(alc.y + arc.y));
    float se2 = __expf(lrelu(alc.z + arc.z));
    float se3 = __expf(lrelu(alc.w + arc.w));
    float rs0 = __fdividef(1.0f, ps.x + se0 + 1e-16f);
    float rs1 = __fdividef(1.0f, ps.y + se1 + 1e-16f);
    float rs2 = __fdividef(1.0f, ps.z + se2 + 1e-16f);
    float rs3 = __fdividef(1.0f, ps.w + se3 + 1e-16f);
    float seh = h < 2 ? (h == 0 ? se0 : se1) : (h == 2 ? se2 : se3);
    float rsh = h < 2 ? (h == 0 ? rs0 : rs1) : (h == 2 ? rs2 : rs3);

    // fold the two edge-parity partial sums
#pragma unroll
    for (int i = 0; i < 8; i++) acc[i] += __shfl_xor_sync(0xffffffffu, acc[i], 16);

    // self term (after fold; both halves compute identically)
    {
        uint4 vc = *(const uint4*)&g_xt1[(size_t)c * 128 + sub * 8];
        float2 f0 = __half22float2(*(__half2*)&vc.x);
        float2 f1 = __half22float2(*(__half2*)&vc.y);
        float2 f2 = __half22float2(*(__half2*)&vc.z);
        float2 f3 = __half22float2(*(__half2*)&vc.w);
        float ws = dc * seh;
        acc[0] += ws * f0.x; acc[1] += ws * f0.y;
        acc[2] += ws * f1.x; acc[3] += ws * f1.y;
        acc[4] += ws * f2.x; acc[5] += ws * f2.y;
        acc[6] += ws * f3.x; acc[7] += ws * f3.y;
    }
    float sc = dc * rsh;

    if (pair == 0) {
        float4 ba = *(const float4*)&b1[sub * 8];
        float4 bb = *(const float4*)&b1[sub * 8 + 4];
        float o[8];
        o[0] = fmaxf(acc[0] * sc + ba.x, 0.f);
        o[1] = fmaxf(acc[1] * sc + ba.y, 0.f);
        o[2] = fmaxf(acc[2] * sc + ba.z, 0.f);
        o[3] = fmaxf(acc[3] * sc + ba.w, 0.f);
        o[4] = fmaxf(acc[4] * sc + bb.x, 0.f);
        o[5] = fmaxf(acc[5] * sc + bb.y, 0.f);
        o[6] = fmaxf(acc[6] * sc + bb.z, 0.f);
        o[7] = fmaxf(acc[7] * sc + bb.w, 0.f);
        uint4 st;
        *(__half2*)&st.x = __floats2half2_rn(o[0], o[1]);
        *(__half2*)&st.y = __floats2half2_rn(o[2], o[3]);
        *(__half2*)&st.z = __floats2half2_rn(o[4], o[5]);
        *(__half2*)&st.w = __floats2half2_rn(o[6], o[7]);
        *(uint4*)&g_h1[(size_t)c * 128 + sub * 8] = st;
    }
}

// ---------------- GEMM2 (tf32, fp16 in) + fused alar2 epilogue, fp16 xt2 out ----------------
__global__ __launch_bounds__(256, 2) void k_gemm2(const float* __restrict__ W2,
                                                  const float* __restrict__ att, int n) {
    __shared__ float Hs[32][132];
    __shared__ float Ws2[32][20];
    int tid = threadIdx.x, lane = tid & 31, wid = tid >> 5;
    int m0 = blockIdx.x * 128;
    int wm = wid * 16;

    float acc[2][4];
#pragma unroll
    for (int nt = 0; nt < 2; nt++)
#pragma unroll
        for (int q = 0; q < 4; q++) acc[nt][q] = 0.f;

    int lm = tid & 127;
    int lkq = (tid >> 7) * 16;
    int wkk = tid >> 3, wc = (tid & 7) * 2;

    for (int k0 = 0; k0 < 128; k0 += 32) {
        uint4 hv0 = make_uint4(0, 0, 0, 0), hv1 = hv0;
        if (m0 + lm < n) {
            const __half* hp = &g_h1[(size_t)(m0 + lm) * 128 + k0 + lkq];
            hv0 = *(const uint4*)hp;
            hv1 = *(const uint4*)(hp + 8);
        }
        {
            const uint32_t* hu = &hv0.x;
#pragma unroll
            for (int j = 0; j < 4; j++) {
                float2 f = __half22float2(*(__half2*)&hu[j]);
                Hs[lkq + j * 2 + 0][lm] = f.x;
                Hs[lkq + j * 2 + 1][lm] = f.y;
            }
            const uint32_t* hu2 = &hv1.x;
#pragma unroll
            for (int j = 0; j < 4; j++) {
                float2 f = __half22float2(*(__half2*)&hu2[j]);
                Hs[lkq + 8 + j * 2 + 0][lm] = f.x;
                Hs[lkq + 8 + j * 2 + 1][lm] = f.y;
            }
        }
        Ws2[wkk][wc]     = f2tf(W2[(size_t)(k0 + wkk) * 16 + wc]);
        Ws2[wkk][wc + 1] = f2tf(W2[(size_t)(k0 + wkk) * 16 + wc + 1]);
        __syncthreads();

#pragma unroll
        for (int kk = 0; kk < 32; kk += 8) {
            int ar = lane >> 2, ak = kk + (lane & 3);
            uint32_t a[4];
            a[0] = __float_as_uint(Hs[ak][wm + ar]);
            a[1] = __float_as_uint(Hs[ak][wm + ar + 8]);
            a[2] = __float_as_uint(Hs[ak + 4][wm + ar]);
            a[3] = __float_as_uint(Hs[ak + 4][wm + ar + 8]);
            uint32_t b0[2], b1[2];
            b0[0] = __float_as_uint(Ws2[ak][ar]);
            b0[1] = __float_as_uint(Ws2[ak + 4][ar]);
            b1[0] = __float_as_uint(Ws2[ak][8 + ar]);
            b1[1] = __float_as_uint(Ws2[ak + 4][8 + ar]);
            mma_tf32(acc[0], a, b0);
            mma_tf32(acc[1], a, b1);
        }
        __syncthreads();
    }

    int ar = lane >> 2, ac = (lane & 3) * 2;
#pragma unroll
    for (int nt = 0; nt < 2; nt++) {
        int r = m0 + wm + ar;
        int c = nt * 8 + ac;
        if (r < n)
            *(__half2*)&g_xt2[(size_t)r * 16 + c] = __floats2half2_rn(acc[nt][0], acc[nt][1]);
        if (r + 8 < n)
            *(__half2*)&g_xt2[(size_t)(r + 8) * 16 + c] = __floats2half2_rn(acc[nt][2], acc[nt][3]);
    }

    // ---- fused alar2 epilogue ----
    float wlv[4], wrv[4];
#pragma unroll
    for (int nt = 0; nt < 2; nt++) {
        int cc = nt * 8 + ac;
        wlv[nt * 2 + 0] = att[cc];
        wlv[nt * 2 + 1] = att[cc + 1];
        wrv[nt * 2 + 0] = att[16 + cc];
        wrv[nt * 2 + 1] = att[16 + cc + 1];
    }
    float alp0 = 0.f, arp0 = 0.f, alp1 = 0.f, arp1 = 0.f;
#pragma unroll
    for (int nt = 0; nt < 2; nt++) {
        alp0 += acc[nt][0] * wlv[nt * 2] + acc[nt][1] * wlv[nt * 2 + 1];
        arp0 += acc[nt][0] * wrv[nt * 2] + acc[nt][1] * wrv[nt * 2 + 1];
        alp1 += acc[nt][2] * wlv[nt * 2] + acc[nt][3] * wlv[nt * 2 + 1];
        arp1 += acc[nt][2] * wrv[nt * 2] + acc[nt][3] * wrv[nt * 2 + 1];
    }
#pragma unroll
    for (int d = 1; d <= 2; d <<= 1) {
        alp0 += __shfl_xor_sync(0xffffffffu, alp0, d);
        arp0 += __shfl_xor_sync(0xffffffffu, arp0, d);
        alp1 += __shfl_xor_sync(0xffffffffu, alp1, d);
        arp1 += __shfl_xor_sync(0xffffffffu, arp1, d);
    }
    if ((lane & 3) == 0) {
        int r = m0 + wm + ar;
        if (r < n)     { g_al2[r] = alp0;     g_ar2[r] = arp0; }
        if (r + 8 < n) { g_al2[r + 8] = alp1; g_ar2[r + 8] = arp1; }
    }
}

// ---------------- layer2 agg: half-warp per node, shfl staging ----------------
__global__ void k_agg2(const float* __restrict__ b2, int n, float* __restrict__ out) {
    int hw = (blockIdx.x * blockDim.x + threadIdx.x) >> 4;   // half-warp = node
    int sub = threadIdx.x & 15;
    unsigned hm = 0xFFFFu << (threadIdx.x & 16);
    bool valid = hw < n;
    int c = valid ? hw : (n - 1);
    float dc = g_dinv[c];
    float alc = g_al2[c];
    int beg = g_off[c], end = g_off[c + 1];

    float ps = 0.f, acc = 0.f;
    for (int t0 = beg; t0 < end; t0 += 16) {
        int j = t0 + sub;
        int r = 0; float wv = 0.f;
        if (j < end) {
            r = __ldg(&g_adj[j]);
            float e = __expf(lrelu(alc + g_ar2[r]));
            ps += e;
            wv = g_dinv[r] * e;
        }
        int cnt = min(16, end - t0);
        for (int u = 0; u < cnt; u++) {
            int ru = __shfl_sync(hm, r, u, 16);
            float wu = __shfl_sync(hm, wv, u, 16);
            acc += wu * __half2float(g_xt2[(size_t)ru * 16 + sub]);
        }
    }
#pragma unroll
    for (int d = 8; d > 0; d >>= 1)
        ps += __shfl_xor_sync(hm, ps, d, 16);
    float se = __expf(lrelu(alc + g_ar2[c]));
    float rs = __fdividef(1.0f, ps + se + 1e-16f);
    acc += dc * se * __half2float(g_xt2[(size_t)c * 16 + sub]);
    if (valid) out[(size_t)c * 16 + sub] = dc * rs * acc + b2[sub];
}

// ---------------- launch (stream-forked: CSR build overlaps GEMM1) ----------------
extern "C" void kernel_launch(void* const* d_in, const int* in_sizes, int n_in,
                              void* d_out, int out_size) {
    const float* x    = (const float*)d_in[0];
    const int*   ei   = (const int*)d_in[1];
    const float* W1   = (const float*)d_in[2];
    const float* att1 = (const float*)d_in[3];
    const float* b1   = (const float*)d_in[4];
    const float* W2   = (const float*)d_in[5];
    const float* att2 = (const float*)d_in[6];
    const float* b2   = (const float*)d_in[7];
    float* out = (float*)d_out;

    int n = in_sizes[0] / 256;
    int e = in_sizes[1] / 2;
    int nb = (n + 1023) / 1024;
    const int T = 256;

    cudaStream_t s2;
    cudaEvent_t evFork, evJoin;
    cudaStreamCreateWithFlags(&s2, cudaStreamNonBlocking);
    cudaEventCreateWithFlags(&evFork, cudaEventDisableTiming);
    cudaEventCreateWithFlags(&evJoin, cudaEventDisableTiming);

    cudaEventRecord(evFork, 0);
    cudaStreamWaitEvent(s2, evFork, 0);

    // chain A (side stream): degree + CSR build
    k_init<<<(n + T - 1) / T, T, 0, s2>>>(n);
    k_deg_count<<<(e + T - 1) / T, T, 0, s2>>>(ei, e);
    k_scan_blocks<<<nb, 1024, 0, s2>>>(n);
    k_scan_add<<<nb, 1024, 0, s2>>>(n, e);
    k_scatter<<<(e + T - 1) / T, T, 0, s2>>>(ei, e);
    cudaEventRecord(evJoin, s2);

    // chain B (main stream): feature transform
    k_gemm1<<<(n + 127) / 128, 256>>>(x, W1, att1, n);

    // join: aggregation needs both chains
    cudaStreamWaitEvent(0, evJoin, 0);
    k_agg1<<<(n * 32 + 255) / 256, 256>>>(b1, n);

    k_gemm2<<<(n + 127) / 128, 256>>>(W2, att2, n);
    k_agg2<<<(n * 16 + 255) / 256, 256>>>(b2, n, out);
}

// round 12
// speedup vs baseline: 1.0114x; 1.0114x over previous
#include <cuda_runtime.h>
#include <cuda_fp16.h>
#include <math.h>
#include <stdint.h>

#define NN 100000
#define EE 1600000
#define NB_SCAN ((NN + 1023) / 1024)

// ---------------- scratch (static device globals) ----------------
__device__ float    g_deg[NN];
__device__ float    g_dinv[NN];
__device__ __half   g_xt1[(size_t)NN * 128];
__device__ float    g_al1[NN * 4];
__device__ float    g_ar1[NN * 4];
__device__ __half   g_h1[(size_t)NN * 128];
__device__ __half   g_xt2[NN * 16];
__device__ float    g_al2[NN];
__device__ float    g_ar2[NN];
// CSR by destination (col)
__device__ int      g_cnt[NN];
__device__ int      g_off[NN + 1];
__device__ int      g_wpos[NN];
__device__ int      g_bsum[NB_SCAN + 1];
__device__ int      g_adj[EE];     // source row only

__device__ __forceinline__ float lrelu(float a) { return a >= 0.f ? a : 0.2f * a; }

__device__ __forceinline__ float f2tf(float f) {
    uint32_t u;
    asm("cvt.rna.tf32.f32 %0, %1;" : "=r"(u) : "f"(f));
    return __uint_as_float(u);
}
__device__ __forceinline__ uint32_t f2tfu(float f) {
    uint32_t u;
    asm("cvt.rna.tf32.f32 %0, %1;" : "=r"(u) : "f"(f));
    return u;
}

__device__ __forceinline__ void mma_tf32(float* c, const uint32_t* a, const uint32_t* b) {
    asm volatile(
        "mma.sync.aligned.m16n8k8.row.col.f32.tf32.tf32.f32 "
        "{%0,%1,%2,%3}, {%4,%5,%6,%7}, {%8,%9}, {%0,%1,%2,%3};"
        : "+f"(c[0]), "+f"(c[1]), "+f"(c[2]), "+f"(c[3])
        : "r"(a[0]), "r"(a[1]), "r"(a[2]), "r"(a[3]), "r"(b[0]), "r"(b[1]));
}

__device__ __forceinline__ void cp16(uint32_t d, const void* s, int sz) {
    asm volatile("cp.async.ca.shared.global [%0], [%1], 16, %2;"
                 :: "r"(d), "l"(s), "r"(sz));
}
__device__ __forceinline__ void cp_commit() {
    asm volatile("cp.async.commit_group;" ::: "memory");
}

// ---------------- init ----------------
__global__ void k_init(int n) {
    int i = blockIdx.x * blockDim.x + threadIdx.x;
    if (i < n) { g_deg[i] = 1.0f; g_cnt[i] = 0; }
}

__global__ void k_deg_count(const int* __restrict__ ei, int e) {
    int i = blockIdx.x * blockDim.x + threadIdx.x;
    if (i < e) {
        atomicAdd(&g_deg[ei[i]], 1.0f);
        atomicAdd(&g_cnt[ei[e + i]], 1);
    }
}

// ---------------- multi-block exclusive scan over g_cnt (+ fused dinv) ----------------
__global__ void k_scan_blocks(int n) {
    __shared__ int warpsums[32];
    int i = blockIdx.x * 1024 + threadIdx.x;
    int lane = threadIdx.x & 31, wid = threadIdx.x >> 5;
    if (i < n) g_dinv[i] = rsqrtf(g_deg[i]);   // fused dinv
    int v = (i < n) ? g_cnt[i] : 0;
    int s = v;
#pragma unroll
    for (int d = 1; d < 32; d <<= 1) {
        int t = __shfl_up_sync(0xffffffffu, s, d);
        if (lane >= d) s += t;
    }
    if (lane == 31) warpsums[wid] = s;
    __syncthreads();
    if (wid == 0) {
        int ws = warpsums[lane];
#pragma unroll
        for (int d = 1; d < 32; d <<= 1) {
            int t = __shfl_up_sync(0xffffffffu, ws, d);
            if (lane >= d) ws += t;
        }
        warpsums[lane] = ws;
    }
    __syncthreads();
    int base = (wid > 0) ? warpsums[wid - 1] : 0;
    int exc = s - v + base;
    if (i < n) g_off[i] = exc;
    if (threadIdx.x == 1023) g_bsum[blockIdx.x] = exc + v;  // raw block total
}

// scan_add computes its own block base from raw totals
__global__ void k_scan_add(int n, int e) {
    __shared__ int sbase;
    if (threadIdx.x == 0) sbase = 0;
    __syncthreads();
    if (threadIdx.x < blockIdx.x) atomicAdd(&sbase, g_bsum[threadIdx.x]);
    __syncthreads();
    int i = blockIdx.x * 1024 + threadIdx.x;
    if (i < n) {
        int o = g_off[i] + sbase;
        g_off[i] = o;
        g_wpos[i] = o;
    }
    if (i == 0) g_off[n] = e;
}

__global__ void k_scatter(const int* __restrict__ ei, int e) {
    int i = blockIdx.x * blockDim.x + threadIdx.x;
    if (i >= e) return;
    int r = ei[i], c = ei[e + i];
    int p = atomicAdd(&g_wpos[c], 1);
    g_adj[p] = r;
}

// ---------------- GEMM1 (tf32, cp.async double-buffered, RNA cvt on fragments) ----------------
__global__ __launch_bounds__(256, 2) void k_gemm1(const float* __restrict__ X,
                                                  const float* __restrict__ W,
                                                  const float* __restrict__ att, int n) {
    __shared__ __align__(16) float Xs[2][128][20];   // [m][k] + pad4
    __shared__ __align__(16) float Ws[2][16][132];   // [k][n] + pad4
    int tid = threadIdx.x, lane = tid & 31, wid = tid >> 5;
    int m0 = blockIdx.x * 128;
    int wm = (wid & 1) * 64, wn = (wid >> 1) * 32;

    float acc[4][4][4];
#pragma unroll
    for (int mt = 0; mt < 4; mt++)
#pragma unroll
        for (int nt = 0; nt < 4; nt++)
#pragma unroll
            for (int q = 0; q < 4; q++) acc[mt][nt][q] = 0.f;

    int lm = tid & 127;
    int lkq = (tid >> 7) * 8;
    int wk = tid >> 4;
    int wq = (tid & 15) * 8;

    bool mok = (m0 + lm < n);
    int xsz = mok ? 16 : 0;
    const float* xsrc = X + (size_t)(m0 + lm) * 256 + lkq;
    const float* wsrc = W + (size_t)wk * 128 + wq;
    uint32_t xd = (uint32_t)__cvta_generic_to_shared(&Xs[0][lm][lkq]);
    uint32_t wd = (uint32_t)__cvta_generic_to_shared(&Ws[0][wk][wq]);
    const uint32_t XST = sizeof(float) * 128 * 20;
    const uint32_t WST = sizeof(float) * 16 * 132;

    cp16(xd, xsrc, xsz);
    cp16(xd + 16, xsrc + 4, xsz);
    cp16(wd, wsrc, 16);
    cp16(wd + 16, wsrc + 4, 16);
    cp_commit();

#pragma unroll 1
    for (int t = 0; t < 16; t++) {
        int s = t & 1;
        if (t + 1 < 16) {
            int s1 = (t + 1) & 1;
            int k0 = (t + 1) * 16;
            cp16(xd + s1 * XST, xsrc + k0, xsz);
            cp16(xd + s1 * XST + 16, xsrc + k0 + 4, xsz);
            cp16(wd + s1 * WST, wsrc + (size_t)k0 * 128, 16);
            cp16(wd + s1 * WST + 16, wsrc + (size_t)k0 * 128 + 4, 16);
            cp_commit();
            asm volatile("cp.async.wait_group 1;" ::: "memory");
        } else {
            asm volatile("cp.async.wait_group 0;" ::: "memory");
        }
        __syncthreads();

#pragma unroll
        for (int kk = 0; kk < 16; kk += 8) {
            int ar = lane >> 2, ak = kk + (lane & 3);
            uint32_t a[4][4], b[4][2];
#pragma unroll
            for (int mt = 0; mt < 4; mt++) {
                int r = wm + mt * 16 + ar;
                a[mt][0] = f2tfu(Xs[s][r][ak]);
                a[mt][1] = f2tfu(Xs[s][r + 8][ak]);
                a[mt][2] = f2tfu(Xs[s][r][ak + 4]);
                a[mt][3] = f2tfu(Xs[s][r + 8][ak + 4]);
            }
#pragma unroll
            for (int nt = 0; nt < 4; nt++) {
                int c = wn + nt * 8 + ar;
                b[nt][0] = f2tfu(Ws[s][ak][c]);
                b[nt][1] = f2tfu(Ws[s][ak + 4][c]);
            }
#pragma unroll
            for (int mt = 0; mt < 4; mt++)
#pragma unroll
                for (int nt = 0; nt < 4; nt++)
                    mma_tf32(acc[mt][nt], a[mt], b[nt]);
        }
        __syncthreads();
    }

    int ar = lane >> 2, ac = (lane & 3) * 2;
#pragma unroll
    for (int mt = 0; mt < 4; mt++) {
        int r = m0 + wm + mt * 16 + ar;
#pragma unroll
        for (int nt = 0; nt < 4; nt++) {
            int c = wn + nt * 8 + ac;
            if (r < n)
                *(__half2*)&g_xt1[(size_t)r * 128 + c] =
                    __floats2half2_rn(acc[mt][nt][0], acc[mt][nt][1]);
            if (r + 8 < n)
                *(__half2*)&g_xt1[(size_t)(r + 8) * 128 + c] =
                    __floats2half2_rn(acc[mt][nt][2], acc[mt][nt][3]);
        }
    }

    // ---- fused alar1 epilogue ----
    int hh = wid >> 1;
    float wlv[8], wrv[8];
#pragma unroll
    for (int nt = 0; nt < 4; nt++) {
        int cc = nt * 8 + ac;
        wlv[nt * 2 + 0] = att[hh * 64 + cc];
        wlv[nt * 2 + 1] = att[hh * 64 + cc + 1];
        wrv[nt * 2 + 0] = att[hh * 64 + 32 + cc];
        wrv[nt * 2 + 1] = att[hh * 64 + 32 + cc + 1];
    }
#pragma unroll
    for (int mt = 0; mt < 4; mt++) {
        float alp0 = 0.f, arp0 = 0.f, alp1 = 0.f, arp1 = 0.f;
#pragma unroll
        for (int nt = 0; nt < 4; nt++) {
            alp0 += acc[mt][nt][0] * wlv[nt * 2] + acc[mt][nt][1] * wlv[nt * 2 + 1];
            arp0 += acc[mt][nt][0] * wrv[nt * 2] + acc[mt][nt][1] * wrv[nt * 2 + 1];
            alp1 += acc[mt][nt][2] * wlv[nt * 2] + acc[mt][nt][3] * wlv[nt * 2 + 1];
            arp1 += acc[mt][nt][2] * wrv[nt * 2] + acc[mt][nt][3] * wrv[nt * 2 + 1];
        }
#pragma unroll
        for (int d = 1; d <= 2; d <<= 1) {
            alp0 += __shfl_xor_sync(0xffffffffu, alp0, d);
            arp0 += __shfl_xor_sync(0xffffffffu, arp0, d);
            alp1 += __shfl_xor_sync(0xffffffffu, alp1, d);
            arp1 += __shfl_xor_sync(0xffffffffu, arp1, d);
        }
        if ((lane & 3) == 0) {
            int r = m0 + wm + mt * 16 + ar;
            if (r < n)     { g_al1[r * 4 + hh] = alp0;       g_ar1[r * 4 + hh] = arp0; }
            if (r + 8 < n) { g_al1[(r + 8) * 4 + hh] = alp1; g_ar1[(r + 8) * 4 + hh] = arp1; }
        }
    }
}

// ---------------- single-sweep fused softmax + aggregation layer1 (fp16 gathers) ----------------
__global__ void k_agg1(const float* __restrict__ b1, int n) {
    __shared__ float sw[8][32][4];
    __shared__ int   sr[8][32];
    int w = (blockIdx.x * blockDim.x + threadIdx.x) >> 5;
    if (w >= n) return;
    int lane = threadIdx.x & 31;
    int wz = (threadIdx.x >> 5) & 7;
    int c = w;
    float dc = g_dinv[c];
    float4 alc = *(const float4*)&g_al1[c * 4];
    float4 arc = *(const float4*)&g_ar1[c * 4];
    int beg = g_off[c], end = g_off[c + 1];
    int h = lane >> 3;

    float4 ps = make_float4(0.f, 0.f, 0.f, 0.f);
    float4 acc = make_float4(0.f, 0.f, 0.f, 0.f);

    for (int t0 = beg; t0 < end; t0 += 32) {
        int j = t0 + lane;
        if (j < end) {
            int r = __ldg(&g_adj[j]);
            float4 ar4 = *(const float4*)&g_ar1[r * 4];
            float di = g_dinv[r];
            float e0 = __expf(lrelu(alc.x + ar4.x));
            float e1 = __expf(lrelu(alc.y + ar4.y));
            float e2 = __expf(lrelu(alc.z + ar4.z));
            float e3 = __expf(lrelu(alc.w + ar4.w));
            ps.x += e0; ps.y += e1; ps.z += e2; ps.w += e3;
            sw[wz][lane][0] = di * e0;
            sw[wz][lane][1] = di * e1;
            sw[wz][lane][2] = di * e2;
            sw[wz][lane][3] = di * e3;
            sr[wz][lane] = r;
        }
        __syncwarp();
        int cnt = min(32, end - t0);
#pragma unroll 8
        for (int u = 0; u < cnt; u++) {
            int r = sr[wz][u];
            float wh = sw[wz][u][h];
            uint2 u2 = *(const uint2*)&g_xt1[(size_t)r * 128 + lane * 4];
            float2 f0 = __half22float2(*(__half2*)&u2.x);
            float2 f1 = __half22float2(*(__half2*)&u2.y);
            acc.x += wh * f0.x; acc.y += wh * f0.y;
            acc.z += wh * f1.x; acc.w += wh * f1.y;
        }
        __syncwarp();
    }

#pragma unroll
    for (int d = 16; d > 0; d >>= 1) {
        ps.x += __shfl_xor_sync(0xffffffffu, ps.x, d);
        ps.y += __shfl_xor_sync(0xffffffffu, ps.y, d);
        ps.z += __shfl_xor_sync(0xffffffffu, ps.z, d);
        ps.w += __shfl_xor_sync(0xffffffffu, ps.w, d);
    }
    float se0 = __expf(lrelu(alc.x + arc.x));
    float se1 = __expf(lrelu(alc.y + arc.y));
    float se2 = __expf(lrelu(alc.z + arc.z));
    float se3 = __expf(lrelu(alc.w + arc.w));
    float rs0 = __fdividef(1.0f, ps.x + se0 + 1e-16f);
    float rs1 = __fdividef(1.0f, ps.y + se1 + 1e-16f);
    float rs2 = __fdividef(1.0f, ps.z + se2 + 1e-16f);
    float rs3 = __fdividef(1.0f, ps.w + se3 + 1e-16f);
    float seh = h < 2 ? (h == 0 ? se0 : se1) : (h == 2 ? se2 : se3);
    float rsh = h < 2 ? (h == 0 ? rs0 : rs1) : (h == 2 ? rs2 : rs3);

    uint2 uc = *(const uint2*)&g_xt1[(size_t)c * 128 + lane * 4];
    float2 c0 = __half22float2(*(__half2*)&uc.x);
    float2 c1 = __half22float2(*(__half2*)&uc.y);
    float wself = dc * seh;
    acc.x += wself * c0.x; acc.y += wself * c0.y;
    acc.z += wself * c1.x; acc.w += wself * c1.y;
    float sc = dc * rsh;

    float4 b = *(const float4*)&b1[lane * 4];
    float ox = fmaxf(acc.x * sc + b.x, 0.f);
    float oy = fmaxf(acc.y * sc + b.y, 0.f);
    float oz = fmaxf(acc.z * sc + b.z, 0.f);
    float ow = fmaxf(acc.w * sc + b.w, 0.f);
    uint2 st;
    *(__half2*)&st.x = __floats2half2_rn(ox, oy);
    *(__half2*)&st.y = __floats2half2_rn(oz, ow);
    *(uint2*)&g_h1[(size_t)c * 128 + lane * 4] = st;
}

// ---------------- GEMM2 (tf32, fp16 in) + fused alar2 epilogue, fp16 xt2 out ----------------
__global__ __launch_bounds__(256, 2) void k_gemm2(const float* __restrict__ W2,
                                                  const float* __restrict__ att, int n) {
    __shared__ float Hs[32][132];
    __shared__ float Ws2[32][20];
    int tid = threadIdx.x, lane = tid & 31, wid = tid >> 5;
    int m0 = blockIdx.x * 128;
    int wm = wid * 16;

    float acc[2][4];
#pragma unroll
    for (int nt = 0; nt < 2; nt++)
#pragma unroll
        for (int q = 0; q < 4; q++) acc[nt][q] = 0.f;

    int lm = tid & 127;
    int lkq = (tid >> 7) * 16;
    int wkk = tid >> 3, wc = (tid & 7) * 2;

    for (int k0 = 0; k0 < 128; k0 += 32) {
        uint4 hv0 = make_uint4(0, 0, 0, 0), hv1 = hv0;
        if (m0 + lm < n) {
            const __half* hp = &g_h1[(size_t)(m0 + lm) * 128 + k0 + lkq];
            hv0 = *(const uint4*)hp;
            hv1 = *(const uint4*)(hp + 8);
        }
        {
            const uint32_t* hu = &hv0.x;
#pragma unroll
            for (int j = 0; j < 4; j++) {
                float2 f = __half22float2(*(__half2*)&hu[j]);
                Hs[lkq + j * 2 + 0][lm] = f.x;
                Hs[lkq + j * 2 + 1][lm] = f.y;
            }
            const uint32_t* hu2 = &hv1.x;
#pragma unroll
            for (int j = 0; j < 4; j++) {
                float2 f = __half22float2(*(__half2*)&hu2[j]);
                Hs[lkq + 8 + j * 2 + 0][lm] = f.x;
                Hs[lkq + 8 + j * 2 + 1][lm] = f.y;
            }
        }
        Ws2[wkk][wc]     = f2tf(W2[(size_t)(k0 + wkk) * 16 + wc]);
        Ws2[wkk][wc + 1] = f2tf(W2[(size_t)(k0 + wkk) * 16 + wc + 1]);
        __syncthreads();

#pragma unroll
        for (int kk = 0; kk < 32; kk += 8) {
            int ar = lane >> 2, ak = kk + (lane & 3);
            uint32_t a[4];
            a[0] = __float_as_uint(Hs[ak][wm + ar]);
            a[1] = __float_as_uint(Hs[ak][wm + ar + 8]);
            a[2] = __float_as_uint(Hs[ak + 4][wm + ar]);
            a[3] = __float_as_uint(Hs[ak + 4][wm + ar + 8]);
            uint32_t b0[2], b1[2];
            b0[0] = __float_as_uint(Ws2[ak][ar]);
            b0[1] = __float_as_uint(Ws2[ak + 4][ar]);
            b1[0] = __float_as_uint(Ws2[ak][8 + ar]);
            b1[1] = __float_as_uint(Ws2[ak + 4][8 + ar]);
            mma_tf32(acc[0], a, b0);
            mma_tf32(acc[1], a, b1);
        }
        __syncthreads();
    }

    int ar = lane >> 2, ac = (lane & 3) * 2;
#pragma unroll
    for (int nt = 0; nt < 2; nt++) {
        int r = m0 + wm + ar;
        int c = nt * 8 + ac;
        if (r < n)
            *(__half2*)&g_xt2[(size_t)r * 16 + c] = __floats2half2_rn(acc[nt][0], acc[nt][1]);
        if (r + 8 < n)
            *(__half2*)&g_xt2[(size_t)(r + 8) * 16 + c] = __floats2half2_rn(acc[nt][2], acc[nt][3]);
    }

    // ---- fused alar2 epilogue ----
    float wlv[4], wrv[4];
#pragma unroll
    for (int nt = 0; nt < 2; nt++) {
        int cc = nt * 8 + ac;
        wlv[nt * 2 + 0] = att[cc];
        wlv[nt * 2 + 1] = att[cc + 1];
        wrv[nt * 2 + 0] = att[16 + cc];
        wrv[nt * 2 + 1] = att[16 + cc + 1];
    }
    float alp0 = 0.f, arp0 = 0.f, alp1 = 0.f, arp1 = 0.f;
#pragma unroll
    for (int nt = 0; nt < 2; nt++) {
        alp0 += acc[nt][0] * wlv[nt * 2] + acc[nt][1] * wlv[nt * 2 + 1];
        arp0 += acc[nt][0] * wrv[nt * 2] + acc[nt][1] * wrv[nt * 2 + 1];
        alp1 += acc[nt][2] * wlv[nt * 2] + acc[nt][3] * wlv[nt * 2 + 1];
        arp1 += acc[nt][2] * wrv[nt * 2] + acc[nt][3] * wrv[nt * 2 + 1];
    }
#pragma unroll
    for (int d = 1; d <= 2; d <<= 1) {
        alp0 += __shfl_xor_sync(0xffffffffu, alp0, d);
        arp0 += __shfl_xor_sync(0xffffffffu, arp0, d);
        alp1 += __shfl_xor_sync(0xffffffffu, alp1, d);
        arp1 += __shfl_xor_sync(0xffffffffu, arp1, d);
    }
    if ((lane & 3) == 0) {
        int r = m0 + wm + ar;
        if (r < n)     { g_al2[r] = alp0;     g_ar2[r] = arp0; }
        if (r + 8 < n) { g_al2[r + 8] = alp1; g_ar2[r + 8] = arp1; }
    }
}

// ---------------- layer2 agg: half-warp per node, shfl staging ----------------
__global__ void k_agg2(const float* __restrict__ b2, int n, float* __restrict__ out) {
    int hw = (blockIdx.x * blockDim.x + threadIdx.x) >> 4;   // half-warp = node
    int sub = threadIdx.x & 15;
    unsigned hm = 0xFFFFu << (threadIdx.x & 16);
    bool valid = hw < n;
    int c = valid ? hw : (n - 1);
    float dc = g_dinv[c];
    float alc = g_al2[c];
    int beg = g_off[c], end = g_off[c + 1];

    float ps = 0.f, acc = 0.f;
    for (int t0 = beg; t0 < end; t0 += 16) {
        int j = t0 + sub;
        int r = 0; float wv = 0.f;
        if (j < end) {
            r = __ldg(&g_adj[j]);
            float e = __expf(lrelu(alc + g_ar2[r]));
            ps += e;
            wv = g_dinv[r] * e;
        }
        int cnt = min(16, end - t0);
        for (int u = 0; u < cnt; u++) {
            int ru = __shfl_sync(hm, r, u, 16);
            float wu = __shfl_sync(hm, wv, u, 16);
            acc += wu * __half2float(g_xt2[(size_t)ru * 16 + sub]);
        }
    }
#pragma unroll
    for (int d = 8; d > 0; d >>= 1)
        ps += __shfl_xor_sync(hm, ps, d, 16);
    float se = __expf(lrelu(alc + g_ar2[c]));
    float rs = __fdividef(1.0f, ps + se + 1e-16f);
    acc += dc * se * __half2float(g_xt2[(size_t)c * 16 + sub]);
    if (valid) out[(size_t)c * 16 + sub] = dc * rs * acc + b2[sub];
}

// ---------------- launch (stream-forked: CSR build overlaps GEMM1) ----------------
extern "C" void kernel_launch(void* const* d_in, const int* in_sizes, int n_in,
                              void* d_out, int out_size) {
    const float* x    = (const float*)d_in[0];
    const int*   ei   = (const int*)d_in[1];
    const float* W1   = (const float*)d_in[2];
    const float* att1 = (const float*)d_in[3];
    const float* b1   = (const float*)d_in[4];
    const float* W2   = (const float*)d_in[5];
    const float* att2 = (const float*)d_in[6];
    const float* b2   = (const float*)d_in[7];
    float* out = (float*)d_out;

    int n = in_sizes[0] / 256;
    int e = in_sizes[1] / 2;
    int nb = (n + 1023) / 1024;
    const int T = 256;

    cudaStream_t s2;
    cudaEvent_t evFork, evJoin;
    cudaStreamCreateWithFlags(&s2, cudaStreamNonBlocking);
    cudaEventCreateWithFlags(&evFork, cudaEventDisableTiming);
    cudaEventCreateWithFlags(&evJoin, cudaEventDisableTiming);

    cudaEventRecord(evFork, 0);
    cudaStreamWaitEvent(s2, evFork, 0);

    // chain A (side stream): degree + CSR build
    k_init<<<(n + T - 1) / T, T, 0, s2>>>(n);
    k_deg_count<<<(e + T - 1) / T, T, 0, s2>>>(ei, e);
    k_scan_blocks<<<nb, 1024, 0, s2>>>(n);
    k_scan_add<<<nb, 1024, 0, s2>>>(n, e);
    k_scatter<<<(e + T - 1) / T, T, 0, s2>>>(ei, e);
    cudaEventRecord(evJoin, s2);

    // chain B (main stream): feature transform
    k_gemm1<<<(n + 127) / 128, 256>>>(x, W1, att1, n);

    // join: aggregation needs both chains
    cudaStreamWaitEvent(0, evJoin, 0);
    k_agg1<<<(n * 32 + 255) / 256, 256>>>(b1, n);

    k_gemm2<<<(n + 127) / 128, 256>>>(W2, att2, n);
    k_agg2<<<(n * 16 + 255) / 256, 256>>>(b2, n, out);
}

// round 13
// speedup vs baseline: 1.0327x; 1.0211x over previous
#include <cuda_runtime.h>
#include <cuda_fp16.h>
#include <math.h>
#include <stdint.h>

#define NN 100000
#define EE 1600000
#define NB_SCAN ((NN + 1023) / 1024)

// ---------------- scratch (static device globals) ----------------
__device__ float    g_deg[NN];
__device__ float    g_dinv[NN];
__device__ __half   g_xt1[(size_t)NN * 128];
__device__ float    g_al1[NN * 4];
__device__ float    g_ar1[NN * 4];
__device__ __half   g_h1[(size_t)NN * 128];
__device__ __half   g_xt2[NN * 16];
__device__ float    g_al2[NN];
__device__ float    g_ar2[NN];
// CSR by destination (col)
__device__ int      g_cnt[NN];
__device__ int      g_off[NN + 1];
__device__ int      g_wpos[NN];
__device__ int      g_bsum[NB_SCAN + 1];
__device__ int      g_adj[EE];     // source row only

__device__ __forceinline__ float lrelu(float a) { return a >= 0.f ? a : 0.2f * a; }

__device__ __forceinline__ uint32_t packh2(float x, float y) {
    __half2 h = __floats2half2_rn(x, y);
    return *(uint32_t*)&h;
}

__device__ __forceinline__ void mma_f16(float* c, const uint32_t* a, const uint32_t* b) {
    asm volatile(
        "mma.sync.aligned.m16n8k16.row.col.f32.f16.f16.f32 "
        "{%0,%1,%2,%3}, {%4,%5,%6,%7}, {%8,%9}, {%0,%1,%2,%3};"
        : "+f"(c[0]), "+f"(c[1]), "+f"(c[2]), "+f"(c[3])
        : "r"(a[0]), "r"(a[1]), "r"(a[2]), "r"(a[3]), "r"(b[0]), "r"(b[1]));
}

__device__ __forceinline__ void cp16(uint32_t d, const void* s, int sz) {
    asm volatile("cp.async.ca.shared.global [%0], [%1], 16, %2;"
                 :: "r"(d), "l"(s), "r"(sz));
}
__device__ __forceinline__ void cp_commit() {
    asm volatile("cp.async.commit_group;" ::: "memory");
}

// ---------------- init ----------------
__global__ void k_init(int n) {
    int i = blockIdx.x * blockDim.x + threadIdx.x;
    if (i < n) { g_deg[i] = 1.0f; g_cnt[i] = 0; }
}

__global__ void k_deg_count(const int* __restrict__ ei, int e) {
    int i = blockIdx.x * blockDim.x + threadIdx.x;
    if (i < e) {
        atomicAdd(&g_deg[ei[i]], 1.0f);
        atomicAdd(&g_cnt[ei[e + i]], 1);
    }
}

// ---------------- multi-block exclusive scan over g_cnt (+ fused dinv) ----------------
__global__ void k_scan_blocks(int n) {
    __shared__ int warpsums[32];
    int i = blockIdx.x * 1024 + threadIdx.x;
    int lane = threadIdx.x & 31, wid = threadIdx.x >> 5;
    if (i < n) g_dinv[i] = rsqrtf(g_deg[i]);
    int v = (i < n) ? g_cnt[i] : 0;
    int s = v;
#pragma unroll
    for (int d = 1; d < 32; d <<= 1) {
        int t = __shfl_up_sync(0xffffffffu, s, d);
        if (lane >= d) s += t;
    }
    if (lane == 31) warpsums[wid] = s;
    __syncthreads();
    if (wid == 0) {
        int ws = warpsums[lane];
#pragma unroll
        for (int d = 1; d < 32; d <<= 1) {
            int t = __shfl_up_sync(0xffffffffu, ws, d);
            if (lane >= d) ws += t;
        }
        warpsums[lane] = ws;
    }
    __syncthreads();
    int base = (wid > 0) ? warpsums[wid - 1] : 0;
    int exc = s - v + base;
    if (i < n) g_off[i] = exc;
    if (threadIdx.x == 1023) g_bsum[blockIdx.x] = exc + v;
}

__global__ void k_scan_add(int n, int e) {
    __shared__ int sbase;
    if (threadIdx.x == 0) sbase = 0;
    __syncthreads();
    if (threadIdx.x < blockIdx.x) atomicAdd(&sbase, g_bsum[threadIdx.x]);
    __syncthreads();
    int i = blockIdx.x * 1024 + threadIdx.x;
    if (i < n) {
        int o = g_off[i] + sbase;
        g_off[i] = o;
        g_wpos[i] = o;
    }
    if (i == 0) g_off[n] = e;
}

__global__ void k_scatter(const int* __restrict__ ei, int e) {
    int i = blockIdx.x * blockDim.x + threadIdx.x;
    if (i >= e) return;
    int r = ei[i], c = ei[e + i];
    int p = atomicAdd(&g_wpos[c], 1);
    g_adj[p] = r;
}

// ---------------- GEMM1 (fp16 mma, cp.async double-buffered) + fused alar1 ----------------
__global__ __launch_bounds__(256, 2) void k_gemm1(const float* __restrict__ X,
                                                  const float* __restrict__ W,
                                                  const float* __restrict__ att, int n) {
    __shared__ __align__(16) float Xs[2][128][20];   // [m][k] + pad4
    __shared__ __align__(16) float Ws[2][16][132];   // [k][n] + pad4
    int tid = threadIdx.x, lane = tid & 31, wid = tid >> 5;
    int m0 = blockIdx.x * 128;
    int wm = (wid & 1) * 64, wn = (wid >> 1) * 32;

    float acc[4][4][4];
#pragma unroll
    for (int mt = 0; mt < 4; mt++)
#pragma unroll
        for (int nt = 0; nt < 4; nt++)
#pragma unroll
            for (int q = 0; q < 4; q++) acc[mt][nt][q] = 0.f;

    int lm = tid & 127;
    int lkq = (tid >> 7) * 8;
    int wk = tid >> 4;
    int wq = (tid & 15) * 8;

    bool mok = (m0 + lm < n);
    int xsz = mok ? 16 : 0;
    const float* xsrc = X + (size_t)(m0 + lm) * 256 + lkq;
    const float* wsrc = W + (size_t)wk * 128 + wq;
    uint32_t xd = (uint32_t)__cvta_generic_to_shared(&Xs[0][lm][lkq]);
    uint32_t wd = (uint32_t)__cvta_generic_to_shared(&Ws[0][wk][wq]);
    const uint32_t XST = sizeof(float) * 128 * 20;
    const uint32_t WST = sizeof(float) * 16 * 132;

    cp16(xd, xsrc, xsz);
    cp16(xd + 16, xsrc + 4, xsz);
    cp16(wd, wsrc, 16);
    cp16(wd + 16, wsrc + 4, 16);
    cp_commit();

#pragma unroll 1
    for (int t = 0; t < 16; t++) {
        int s = t & 1;
        if (t + 1 < 16) {
            int s1 = (t + 1) & 1;
            int k0 = (t + 1) * 16;
            cp16(xd + s1 * XST, xsrc + k0, xsz);
            cp16(xd + s1 * XST + 16, xsrc + k0 + 4, xsz);
            cp16(wd + s1 * WST, wsrc + (size_t)k0 * 128, 16);
            cp16(wd + s1 * WST + 16, wsrc + (size_t)k0 * 128 + 4, 16);
            cp_commit();
            asm volatile("cp.async.wait_group 1;" ::: "memory");
        } else {
            asm volatile("cp.async.wait_group 0;" ::: "memory");
        }
        __syncthreads();

        // one m16n8k16 step covers the whole 16-wide k tile
        {
            int gp = lane >> 2, tq2 = (lane & 3) * 2;
            uint32_t a[4][4], b[4][2];
#pragma unroll
            for (int mt = 0; mt < 4; mt++) {
                int r = wm + mt * 16 + gp;
                float2 x0 = *(const float2*)&Xs[s][r][tq2];
                float2 x1 = *(const float2*)&Xs[s][r + 8][tq2];
                float2 x2 = *(const float2*)&Xs[s][r][tq2 + 8];
                float2 x3 = *(const float2*)&Xs[s][r + 8][tq2 + 8];
                a[mt][0] = packh2(x0.x, x0.y);
                a[mt][1] = packh2(x1.x, x1.y);
                a[mt][2] = packh2(x2.x, x2.y);
                a[mt][3] = packh2(x3.x, x3.y);
            }
#pragma unroll
            for (int nt = 0; nt < 4; nt++) {
                int c = wn + nt * 8 + gp;
                b[nt][0] = packh2(Ws[s][tq2][c], Ws[s][tq2 + 1][c]);
                b[nt][1] = packh2(Ws[s][tq2 + 8][c], Ws[s][tq2 + 9][c]);
            }
#pragma unroll
            for (int mt = 0; mt < 4; mt++)
#pragma unroll
                for (int nt = 0; nt < 4; nt++)
                    mma_f16(acc[mt][nt], a[mt], b[nt]);
        }
        __syncthreads();
    }

    int ar = lane >> 2, ac = (lane & 3) * 2;
#pragma unroll
    for (int mt = 0; mt < 4; mt++) {
        int r = m0 + wm + mt * 16 + ar;
#pragma unroll
        for (int nt = 0; nt < 4; nt++) {
            int c = wn + nt * 8 + ac;
            if (r < n)
                *(__half2*)&g_xt1[(size_t)r * 128 + c] =
                    __floats2half2_rn(acc[mt][nt][0], acc[mt][nt][1]);
            if (r + 8 < n)
                *(__half2*)&g_xt1[(size_t)(r + 8) * 128 + c] =
                    __floats2half2_rn(acc[mt][nt][2], acc[mt][nt][3]);
        }
    }

    // ---- fused alar1 epilogue ----
    int hh = wid >> 1;
    float wlv[8], wrv[8];
#pragma unroll
    for (int nt = 0; nt < 4; nt++) {
        int cc = nt * 8 + ac;
        wlv[nt * 2 + 0] = att[hh * 64 + cc];
        wlv[nt * 2 + 1] = att[hh * 64 + cc + 1];
        wrv[nt * 2 + 0] = att[hh * 64 + 32 + cc];
        wrv[nt * 2 + 1] = att[hh * 64 + 32 + cc + 1];
    }
#pragma unroll
    for (int mt = 0; mt < 4; mt++) {
        float alp0 = 0.f, arp0 = 0.f, alp1 = 0.f, arp1 = 0.f;
#pragma unroll
        for (int nt = 0; nt < 4; nt++) {
            alp0 += acc[mt][nt][0] * wlv[nt * 2] + acc[mt][nt][1] * wlv[nt * 2 + 1];
            arp0 += acc[mt][nt][0] * wrv[nt * 2] + acc[mt][nt][1] * wrv[nt * 2 + 1];
            alp1 += acc[mt][nt][2] * wlv[nt * 2] + acc[mt][nt][3] * wlv[nt * 2 + 1];
            arp1 += acc[mt][nt][2] * wrv[nt * 2] + acc[mt][nt][3] * wrv[nt * 2 + 1];
        }
#pragma unroll
        for (int d = 1; d <= 2; d <<= 1) {
            alp0 += __shfl_xor_sync(0xffffffffu, alp0, d);
            arp0 += __shfl_xor_sync(0xffffffffu, arp0, d);
            alp1 += __shfl_xor_sync(0xffffffffu, alp1, d);
            arp1 += __shfl_xor_sync(0xffffffffu, arp1, d);
        }
        if ((lane & 3) == 0) {
            int r = m0 + wm + mt * 16 + ar;
            if (r < n)     { g_al1[r * 4 + hh] = alp0;       g_ar1[r * 4 + hh] = arp0; }
            if (r + 8 < n) { g_al1[(r + 8) * 4 + hh] = alp1; g_ar1[(r + 8) * 4 + hh] = arp1; }
        }
    }
}

// ---------------- single-sweep fused softmax + aggregation layer1 (fp16 gathers) ----------------
__global__ void k_agg1(const float* __restrict__ b1, int n) {
    __shared__ float sw[8][32][4];
    __shared__ int   sr[8][32];
    int w = (blockIdx.x * blockDim.x + threadIdx.x) >> 5;
    if (w >= n) return;
    int lane = threadIdx.x & 31;
    int wz = (threadIdx.x >> 5) & 7;
    int c = w;
    float dc = g_dinv[c];
    float4 alc = *(const float4*)&g_al1[c * 4];
    float4 arc = *(const float4*)&g_ar1[c * 4];
    int beg = g_off[c], end = g_off[c + 1];
    int h = lane >> 3;

    float4 ps = make_float4(0.f, 0.f, 0.f, 0.f);
    float4 acc = make_float4(0.f, 0.f, 0.f, 0.f);

    for (int t0 = beg; t0 < end; t0 += 32) {
        int j = t0 + lane;
        if (j < end) {
            int r = __ldg(&g_adj[j]);
            float4 ar4 = *(const float4*)&g_ar1[r * 4];
            float di = g_dinv[r];
            float e0 = __expf(lrelu(alc.x + ar4.x));
            float e1 = __expf(lrelu(alc.y + ar4.y));
            float e2 = __expf(lrelu(alc.z + ar4.z));
            float e3 = __expf(lrelu(alc.w + ar4.w));
            ps.x += e0; ps.y += e1; ps.z += e2; ps.w += e3;
            sw[wz][lane][0] = di * e0;
            sw[wz][lane][1] = di * e1;
            sw[wz][lane][2] = di * e2;
            sw[wz][lane][3] = di * e3;
            sr[wz][lane] = r;
        }
        __syncwarp();
        int cnt = min(32, end - t0);
#pragma unroll 4
        for (int u = 0; u < cnt; u++) {
            int r = sr[wz][u];
            float wh = sw[wz][u][h];
            uint2 u2 = *(const uint2*)&g_xt1[(size_t)r * 128 + lane * 4];
            float2 f0 = __half22float2(*(__half2*)&u2.x);
            float2 f1 = __half22float2(*(__half2*)&u2.y);
            acc.x += wh * f0.x; acc.y += wh * f0.y;
            acc.z += wh * f1.x; acc.w += wh * f1.y;
        }
        __syncwarp();
    }

#pragma unroll
    for (int d = 16; d > 0; d >>= 1) {
        ps.x += __shfl_xor_sync(0xffffffffu, ps.x, d);
        ps.y += __shfl_xor_sync(0xffffffffu, ps.y, d);
        ps.z += __shfl_xor_sync(0xffffffffu, ps.z, d);
        ps.w += __shfl_xor_sync(0xffffffffu, ps.w, d);
    }
    float se0 = __expf(lrelu(alc.x + arc.x));
    float se1 = __expf(lrelu(alc.y + arc.y));
    float se2 = __expf(lrelu(alc.z + arc.z));
    float se3 = __expf(lrelu(alc.w + arc.w));
    float rs0 = __fdividef(1.0f, ps.x + se0 + 1e-16f);
    float rs1 = __fdividef(1.0f, ps.y + se1 + 1e-16f);
    float rs2 = __fdividef(1.0f, ps.z + se2 + 1e-16f);
    float rs3 = __fdividef(1.0f, ps.w + se3 + 1e-16f);
    float seh = h < 2 ? (h == 0 ? se0 : se1) : (h == 2 ? se2 : se3);
    float rsh = h < 2 ? (h == 0 ? rs0 : rs1) : (h == 2 ? rs2 : rs3);

    uint2 uc = *(const uint2*)&g_xt1[(size_t)c * 128 + lane * 4];
    float2 c0 = __half22float2(*(__half2*)&uc.x);
    float2 c1 = __half22float2(*(__half2*)&uc.y);
    float wself = dc * seh;
    acc.x += wself * c0.x; acc.y += wself * c0.y;
    acc.z += wself * c1.x; acc.w += wself * c1.y;
    float sc = dc * rsh;

    float4 b = *(const float4*)&b1[lane * 4];
    float ox = fmaxf(acc.x * sc + b.x, 0.f);
    float oy = fmaxf(acc.y * sc + b.y, 0.f);
    float oz = fmaxf(acc.z * sc + b.z, 0.f);
    float ow = fmaxf(acc.w * sc + b.w, 0.f);
    uint2 st;
    *(__half2*)&st.x = __floats2half2_rn(ox, oy);
    *(__half2*)&st.y = __floats2half2_rn(oz, ow);
    *(uint2*)&g_h1[(size_t)c * 128 + lane * 4] = st;
}

// ---------------- GEMM2 (fp16 mma, zero-convert H) + fused alar2 epilogue ----------------
__global__ __launch_bounds__(256, 2) void k_gemm2(const float* __restrict__ W2,
                                                  const float* __restrict__ att, int n) {
    __shared__ __align__(16) __half Hs[128][56];   // [m][k:32 + pad:24] -> 112B rows
    __shared__ __half Ws2t[16][40];                // [n][k:32 + pad:8]
    int tid = threadIdx.x, lane = tid & 31, wid = tid >> 5;
    int m0 = blockIdx.x * 128;
    int wm = wid * 16;

    float acc[2][4];
#pragma unroll
    for (int nt = 0; nt < 2; nt++)
#pragma unroll
        for (int q = 0; q < 4; q++) acc[nt][q] = 0.f;

    int lm = tid & 127;
    int lkq = (tid >> 7) * 16;
    int wkk = tid >> 3, wc = (tid & 7) * 2;

    for (int k0 = 0; k0 < 128; k0 += 32) {
        uint4 hv0 = make_uint4(0, 0, 0, 0), hv1 = hv0;
        if (m0 + lm < n) {
            const __half* hp = &g_h1[(size_t)(m0 + lm) * 128 + k0 + lkq];
            hv0 = *(const uint4*)hp;
            hv1 = *(const uint4*)(hp + 8);
        }
        *(uint4*)&Hs[lm][lkq] = hv0;       // halves lkq..lkq+7 (raw copy, no cvt)
        *(uint4*)&Hs[lm][lkq + 8] = hv1;
        Ws2t[wc][wkk]     = __float2half_rn(W2[(size_t)(k0 + wkk) * 16 + wc]);
        Ws2t[wc + 1][wkk] = __float2half_rn(W2[(size_t)(k0 + wkk) * 16 + wc + 1]);
        __syncthreads();

        int gp = lane >> 2, tq2 = (lane & 3) * 2;
#pragma unroll
        for (int ks = 0; ks < 2; ks++) {
            int kb = ks * 16;
            uint32_t a[4];
            int r = wm + gp;
            a[0] = *(const uint32_t*)&Hs[r][kb + tq2];
            a[1] = *(const uint32_t*)&Hs[r + 8][kb + tq2];
            a[2] = *(const uint32_t*)&Hs[r][kb + tq2 + 8];
            a[3] = *(const uint32_t*)&Hs[r + 8][kb + tq2 + 8];
            uint32_t b0[2], b1[2];
            b0[0] = *(const uint32_t*)&Ws2t[gp][kb + tq2];
            b0[1] = *(const uint32_t*)&Ws2t[gp][kb + tq2 + 8];
            b1[0] = *(const uint32_t*)&Ws2t[8 + gp][kb + tq2];
            b1[1] = *(const uint32_t*)&Ws2t[8 + gp][kb + tq2 + 8];
            mma_f16(acc[0], a, b0);
            mma_f16(acc[1], a, b1);
        }
        __syncthreads();
    }

    int ar = lane >> 2, ac = (lane & 3) * 2;
#pragma unroll
    for (int nt = 0; nt < 2; nt++) {
        int r = m0 + wm + ar;
        int c = nt * 8 + ac;
        if (r < n)
            *(__half2*)&g_xt2[(size_t)r * 16 + c] = __floats2half2_rn(acc[nt][0], acc[nt][1]);
        if (r + 8 < n)
            *(__half2*)&g_xt2[(size_t)(r + 8) * 16 + c] = __floats2half2_rn(acc[nt][2], acc[nt][3]);
    }

    // ---- fused alar2 epilogue ----
    float wlv[4], wrv[4];
#pragma unroll
    for (int nt = 0; nt < 2; nt++) {
        int cc = nt * 8 + ac;
        wlv[nt * 2 + 0] = att[cc];
        wlv[nt * 2 + 1] = att[cc + 1];
        wrv[nt * 2 + 0] = att[16 + cc];
        wrv[nt * 2 + 1] = att[16 + cc + 1];
    }
    float alp0 = 0.f, arp0 = 0.f, alp1 = 0.f, arp1 = 0.f;
#pragma unroll
    for (int nt = 0; nt < 2; nt++) {
        alp0 += acc[nt][0] * wlv[nt * 2] + acc[nt][1] * wlv[nt * 2 + 1];
        arp0 += acc[nt][0] * wrv[nt * 2] + acc[nt][1] * wrv[nt * 2 + 1];
        alp1 += acc[nt][2] * wlv[nt * 2] + acc[nt][3] * wlv[nt * 2 + 1];
        arp1 += acc[nt][2] * wrv[nt * 2] + acc[nt][3] * wrv[nt * 2 + 1];
    }
#pragma unroll
    for (int d = 1; d <= 2; d <<= 1) {
        alp0 += __shfl_xor_sync(0xffffffffu, alp0, d);
        arp0 += __shfl_xor_sync(0xffffffffu, arp0, d);
        alp1 += __shfl_xor_sync(0xffffffffu, alp1, d);
        arp1 += __shfl_xor_sync(0xffffffffu, arp1, d);
    }
    if ((lane & 3) == 0) {
        int r = m0 + wm + ar;
        if (r < n)     { g_al2[r] = alp0;     g_ar2[r] = arp0; }
        if (r + 8 < n) { g_al2[r + 8] = alp1; g_ar2[r + 8] = arp1; }
    }
}

// ---------------- layer2 agg: half-warp per node, shfl staging ----------------
__global__ void k_agg2(const float* __restrict__ b2, int n, float* __restrict__ out) {
    int hw = (blockIdx.x * blockDim.x + threadIdx.x) >> 4;
    int sub = threadIdx.x & 15;
    unsigned hm = 0xFFFFu << (threadIdx.x & 16);
    bool valid = hw < n;
    int c = valid ? hw : (n - 1);
    float dc = g_dinv[c];
    float alc = g_al2[c];
    int beg = g_off[c], end = g_off[c + 1];

    float ps = 0.f, acc = 0.f;
    for (int t0 = beg; t0 < end; t0 += 16) {
        int j = t0 + sub;
        int r = 0; float wv = 0.f;
        if (j < end) {
            r = __ldg(&g_adj[j]);
            float e = __expf(lrelu(alc + g_ar2[r]));
            ps += e;
            wv = g_dinv[r] * e;
        }
        int cnt = min(16, end - t0);
        for (int u = 0; u < cnt; u++) {
            int ru = __shfl_sync(hm, r, u, 16);
            float wu = __shfl_sync(hm, wv, u, 16);
            acc += wu * __half2float(g_xt2[(size_t)ru * 16 + sub]);
        }
    }
#pragma unroll
    for (int d = 8; d > 0; d >>= 1)
        ps += __shfl_xor_sync(hm, ps, d, 16);
    float se = __expf(lrelu(alc + g_ar2[c]));
    float rs = __fdividef(1.0f, ps + se + 1e-16f);
    acc += dc * se * __half2float(g_xt2[(size_t)c * 16 + sub]);
    if (valid) out[(size_t)c * 16 + sub] = dc * rs * acc + b2[sub];
}

// ---------------- launch (stream-forked; gemm1 at submission index 3 for ncu) ----------------
extern "C" void kernel_launch(void* const* d_in, const int* in_sizes, int n_in,
                              void* d_out, int out_size) {
    const float* x    = (const float*)d_in[0];
    const int*   ei   = (const int*)d_in[1];
    const float* W1   = (const float*)d_in[2];
    const float* att1 = (const float*)d_in[3];
    const float* b1   = (const float*)d_in[4];
    const float* W2   = (const float*)d_in[5];
    const float* att2 = (const float*)d_in[6];
    const float* b2   = (const float*)d_in[7];
    float* out = (float*)d_out;

    int n = in_sizes[0] / 256;
    int e = in_sizes[1] / 2;
    int nb = (n + 1023) / 1024;
    const int T = 256;

    cudaStream_t s2;
    cudaEvent_t evFork, evJoin;
    cudaStreamCreateWithFlags(&s2, cudaStreamNonBlocking);
    cudaEventCreateWithFlags(&evFork, cudaEventDisableTiming);
    cudaEventCreateWithFlags(&evJoin, cudaEventDisableTiming);

    cudaEventRecord(evFork, 0);
    cudaStreamWaitEvent(s2, evFork, 0);

    // chain A (side stream) begins
    k_init<<<(n + T - 1) / T, T, 0, s2>>>(n);                 // idx 0
    k_deg_count<<<(e + T - 1) / T, T, 0, s2>>>(ei, e);        // idx 1
    k_scan_blocks<<<nb, 1024, 0, s2>>>(n);                    // idx 2
    // chain B (main stream) — submitted here so ncu (capture idx 3) profiles it
    k_gemm1<<<(n + 127) / 128, 256>>>(x, W1, att1, n);        // idx 3
    // chain A continues
    k_scan_add<<<nb, 1024, 0, s2>>>(n, e);                    // idx 4
    k_scatter<<<(e + T - 1) / T, T, 0, s2>>>(ei, e);          // idx 5
    cudaEventRecord(evJoin, s2);

    // join: aggregation needs both chains
    cudaStreamWaitEvent(0, evJoin, 0);
    k_agg1<<<(n * 32 + 255) / 256, 256>>>(b1, n);

    k_gemm2<<<(n + 127) / 128, 256>>>(W2, att2, n);
    k_agg2<<<(n * 16 + 255) / 256, 256>>>(b2, n, out);
}

// round 14
// speedup vs baseline: 1.1145x; 1.0792x over previous
#include <cuda_runtime.h>
#include <cuda_fp16.h>
#include <math.h>
#include <stdint.h>

#define NN 100000
#define EE 1600000
#define NB_SCAN ((NN + 1023) / 1024)

// ---------------- scratch (static device globals) ----------------
__device__ float    g_deg[NN];
__device__ float    g_dinv[NN];
__device__ __half   g_xt1[(size_t)NN * 128];
__device__ float    g_al1[NN * 4];
__device__ float    g_ar1[NN * 4];
__device__ __half   g_h1[(size_t)NN * 128];
__device__ __half   g_xt2[NN * 16];
__device__ float    g_al2[NN];
__device__ float    g_ar2[NN];
// CSR by destination (col)
__device__ int      g_cnt[NN];
__device__ int      g_off[NN + 1];
__device__ int      g_wpos[NN];
__device__ int      g_bsum[NB_SCAN + 1];
__device__ int      g_adj[EE];     // source row only

__device__ __forceinline__ float lrelu(float a) { return a >= 0.f ? a : 0.2f * a; }

__device__ __forceinline__ uint32_t packh2(float x, float y) {
    __half2 h = __floats2half2_rn(x, y);
    return *(uint32_t*)&h;
}

__device__ __forceinline__ void mma_f16(float* c, const uint32_t* a, const uint32_t* b) {
    asm volatile(
        "mma.sync.aligned.m16n8k16.row.col.f32.f16.f16.f32 "
        "{%0,%1,%2,%3}, {%4,%5,%6,%7}, {%8,%9}, {%0,%1,%2,%3};"
        : "+f"(c[0]), "+f"(c[1]), "+f"(c[2]), "+f"(c[3])
        : "r"(a[0]), "r"(a[1]), "r"(a[2]), "r"(a[3]), "r"(b[0]), "r"(b[1]));
}

// ---------------- init ----------------
__global__ void k_init(int n) {
    int i = blockIdx.x * blockDim.x + threadIdx.x;
    if (i < n) { g_deg[i] = 1.0f; g_cnt[i] = 0; }
}

__global__ void k_deg_count(const int* __restrict__ ei, int e) {
    int i = blockIdx.x * blockDim.x + threadIdx.x;
    if (i < e) {
        atomicAdd(&g_deg[ei[i]], 1.0f);
        atomicAdd(&g_cnt[ei[e + i]], 1);
    }
}

// ---------------- multi-block exclusive scan over g_cnt (+ fused dinv) ----------------
__global__ void k_scan_blocks(int n) {
    __shared__ int warpsums[32];
    int i = blockIdx.x * 1024 + threadIdx.x;
    int lane = threadIdx.x & 31, wid = threadIdx.x >> 5;
    if (i < n) g_dinv[i] = rsqrtf(g_deg[i]);
    int v = (i < n) ? g_cnt[i] : 0;
    int s = v;
#pragma unroll
    for (int d = 1; d < 32; d <<= 1) {
        int t = __shfl_up_sync(0xffffffffu, s, d);
        if (lane >= d) s += t;
    }
    if (lane == 31) warpsums[wid] = s;
    __syncthreads();
    if (wid == 0) {
        int ws = warpsums[lane];
#pragma unroll
        for (int d = 1; d < 32; d <<= 1) {
            int t = __shfl_up_sync(0xffffffffu, ws, d);
            if (lane >= d) ws += t;
        }
        warpsums[lane] = ws;
    }
    __syncthreads();
    int base = (wid > 0) ? warpsums[wid - 1] : 0;
    int exc = s - v + base;
    if (i < n) g_off[i] = exc;
    if (threadIdx.x == 1023) g_bsum[blockIdx.x] = exc + v;
}

__global__ void k_scan_add(int n, int e) {
    __shared__ int sbase;
    if (threadIdx.x == 0) sbase = 0;
    __syncthreads();
    if (threadIdx.x < blockIdx.x) atomicAdd(&sbase, g_bsum[threadIdx.x]);
    __syncthreads();
    int i = blockIdx.x * 1024 + threadIdx.x;
    if (i < n) {
        int o = g_off[i] + sbase;
        g_off[i] = o;
        g_wpos[i] = o;
    }
    if (i == 0) g_off[n] = e;
}

__global__ void k_scatter(const int* __restrict__ ei, int e) {
    int i = blockIdx.x * blockDim.x + threadIdx.x;
    if (i >= e) return;
    int r = ei[i], c = ei[e + i];
    int p = atomicAdd(&g_wpos[c], 1);
    g_adj[p] = r;
}

// ---------------- GEMM1: fp16 smem, k32 tiles, single sync per tile ----------------
// xt1[n,128] = X[n,256] @ W1[256,128]; fp32 gmem -> regs -> half2 smem -> mma.f16
__global__ __launch_bounds__(256, 2) void k_gemm1(const float* __restrict__ X,
                                                  const float* __restrict__ W,
                                                  const float* __restrict__ att, int n) {
    __shared__ __align__(16) __half   Xs[2][128][40];    // [m][k:32 + pad:8]
    __shared__ __align__(16) uint32_t Wsp[2][16][136];   // [k2][n:128 + pad:8], half2-packed k pairs
    int tid = threadIdx.x, lane = tid & 31, wid = tid >> 5;
    int m0 = blockIdx.x * 128;
    int wm = (wid & 1) * 64, wn = (wid >> 1) * 32;

    float acc[4][4][4];
#pragma unroll
    for (int mt = 0; mt < 4; mt++)
#pragma unroll
        for (int nt = 0; nt < 4; nt++)
#pragma unroll
            for (int q = 0; q < 4; q++) acc[mt][nt][q] = 0.f;

    // copy roles
    int lm = tid & 127, ks = (tid >> 7) * 16;     // X: row lm, 16 k-values at ks
    int k2 = tid >> 4, n0 = (tid & 15) * 8;       // W: k-pair row k2, 8 n-values at n0
    bool mok = (m0 + lm < n);
    const float* xp  = X + (size_t)(m0 + lm) * 256 + ks;
    const float* wp0 = W + (size_t)(2 * k2) * 128 + n0;
    const float* wp1 = wp0 + 128;

    float4 xv[4], wa[2], wb[2];
    // preload tile 0
#pragma unroll
    for (int j = 0; j < 4; j++)
        xv[j] = mok ? *(const float4*)(xp + j * 4) : make_float4(0.f, 0.f, 0.f, 0.f);
    wa[0] = *(const float4*)(wp0);     wa[1] = *(const float4*)(wp0 + 4);
    wb[0] = *(const float4*)(wp1);     wb[1] = *(const float4*)(wp1 + 4);

    int gp = lane >> 2, q = lane & 3, tq2 = q * 2;

#pragma unroll 1
    for (int t = 0; t < 8; t++) {
        int s = t & 1;
        // store current tile (pack to fp16)
#pragma unroll
        for (int j = 0; j < 4; j++) {
            uint2 u;
            u.x = packh2(xv[j].x, xv[j].y);
            u.y = packh2(xv[j].z, xv[j].w);
            *(uint2*)&Xs[s][lm][ks + j * 4] = u;
        }
        {
            uint4 u0, u1;
            u0.x = packh2(wa[0].x, wb[0].x); u0.y = packh2(wa[0].y, wb[0].y);
            u0.z = packh2(wa[0].z, wb[0].z); u0.w = packh2(wa[0].w, wb[0].w);
            u1.x = packh2(wa[1].x, wb[1].x); u1.y = packh2(wa[1].y, wb[1].y);
            u1.z = packh2(wa[1].z, wb[1].z); u1.w = packh2(wa[1].w, wb[1].w);
            *(uint4*)&Wsp[s][k2][n0] = u0;
            *(uint4*)&Wsp[s][k2][n0 + 4] = u1;
        }
        __syncthreads();

        // prefetch next tile
        if (t < 7) {
            int kn = (t + 1) * 32;
#pragma unroll
            for (int j = 0; j < 4; j++)
                xv[j] = mok ? *(const float4*)(xp + kn + j * 4) : make_float4(0.f, 0.f, 0.f, 0.f);
            wa[0] = *(const float4*)(wp0 + (size_t)kn * 128);
            wa[1] = *(const float4*)(wp0 + (size_t)kn * 128 + 4);
            wb[0] = *(const float4*)(wp1 + (size_t)kn * 128);
            wb[1] = *(const float4*)(wp1 + (size_t)kn * 128 + 4);
        }

        // 2 k16 steps
#pragma unroll
        for (int ks2 = 0; ks2 < 2; ks2++) {
            int kb = ks2 * 16;
            uint32_t a[4][4], b[4][2];
#pragma unroll
            for (int mt = 0; mt < 4; mt++) {
                int r = wm + mt * 16 + gp;
                a[mt][0] = *(const uint32_t*)&Xs[s][r][kb + tq2];
                a[mt][1] = *(const uint32_t*)&Xs[s][r + 8][kb + tq2];
                a[mt][2] = *(const uint32_t*)&Xs[s][r][kb + tq2 + 8];
                a[mt][3] = *(const uint32_t*)&Xs[s][r + 8][kb + tq2 + 8];
            }
#pragma unroll
            for (int nt = 0; nt < 4; nt++) {
                int c = wn + nt * 8 + gp;
                b[nt][0] = Wsp[s][kb / 2 + q][c];
                b[nt][1] = Wsp[s][kb / 2 + q + 4][c];
            }
#pragma unroll
            for (int mt = 0; mt < 4; mt++)
#pragma unroll
                for (int nt = 0; nt < 4; nt++)
                    mma_f16(acc[mt][nt], a[mt], b[nt]);
        }
        // single sync per tile: next iteration's store targets the other stage,
        // whose readers were already ordered by this tile's sync
    }

    int ar = lane >> 2, ac = (lane & 3) * 2;
#pragma unroll
    for (int mt = 0; mt < 4; mt++) {
        int r = m0 + wm + mt * 16 + ar;
#pragma unroll
        for (int nt = 0; nt < 4; nt++) {
            int c = wn + nt * 8 + ac;
            if (r < n)
                *(__half2*)&g_xt1[(size_t)r * 128 + c] =
                    __floats2half2_rn(acc[mt][nt][0], acc[mt][nt][1]);
            if (r + 8 < n)
                *(__half2*)&g_xt1[(size_t)(r + 8) * 128 + c] =
                    __floats2half2_rn(acc[mt][nt][2], acc[mt][nt][3]);
        }
    }

    // ---- fused alar1 epilogue ----
    int hh = wid >> 1;
    float wlv[8], wrv[8];
#pragma unroll
    for (int nt = 0; nt < 4; nt++) {
        int cc = nt * 8 + ac;
        wlv[nt * 2 + 0] = att[hh * 64 + cc];
        wlv[nt * 2 + 1] = att[hh * 64 + cc + 1];
        wrv[nt * 2 + 0] = att[hh * 64 + 32 + cc];
        wrv[nt * 2 + 1] = att[hh * 64 + 32 + cc + 1];
    }
#pragma unroll
    for (int mt = 0; mt < 4; mt++) {
        float alp0 = 0.f, arp0 = 0.f, alp1 = 0.f, arp1 = 0.f;
#pragma unroll
        for (int nt = 0; nt < 4; nt++) {
            alp0 += acc[mt][nt][0] * wlv[nt * 2] + acc[mt][nt][1] * wlv[nt * 2 + 1];
            arp0 += acc[mt][nt][0] * wrv[nt * 2] + acc[mt][nt][1] * wrv[nt * 2 + 1];
            alp1 += acc[mt][nt][2] * wlv[nt * 2] + acc[mt][nt][3] * wlv[nt * 2 + 1];
            arp1 += acc[mt][nt][2] * wrv[nt * 2] + acc[mt][nt][3] * wrv[nt * 2 + 1];
        }
#pragma unroll
        for (int d = 1; d <= 2; d <<= 1) {
            alp0 += __shfl_xor_sync(0xffffffffu, alp0, d);
            arp0 += __shfl_xor_sync(0xffffffffu, arp0, d);
            alp1 += __shfl_xor_sync(0xffffffffu, alp1, d);
            arp1 += __shfl_xor_sync(0xffffffffu, arp1, d);
        }
        if ((lane & 3) == 0) {
            int r = m0 + wm + mt * 16 + ar;
            if (r < n)     { g_al1[r * 4 + hh] = alp0;       g_ar1[r * 4 + hh] = arp0; }
            if (r + 8 < n) { g_al1[(r + 8) * 4 + hh] = alp1; g_ar1[(r + 8) * 4 + hh] = arp1; }
        }
    }
}

// ---------------- single-sweep fused softmax + aggregation layer1 (fp16 gathers) ----------------
__global__ void k_agg1(const float* __restrict__ b1, int n) {
    __shared__ float sw[8][32][4];
    __shared__ int   sr[8][32];
    int w = (blockIdx.x * blockDim.x + threadIdx.x) >> 5;
    if (w >= n) return;
    int lane = threadIdx.x & 31;
    int wz = (threadIdx.x >> 5) & 7;
    int c = w;
    float dc = g_dinv[c];
    float4 alc = *(const float4*)&g_al1[c * 4];
    float4 arc = *(const float4*)&g_ar1[c * 4];
    int beg = g_off[c], end = g_off[c + 1];
    int h = lane >> 3;

    float4 ps = make_float4(0.f, 0.f, 0.f, 0.f);
    float4 acc = make_float4(0.f, 0.f, 0.f, 0.f);

    for (int t0 = beg; t0 < end; t0 += 32) {
        int j = t0 + lane;
        if (j < end) {
            int r = __ldg(&g_adj[j]);
            float4 ar4 = *(const float4*)&g_ar1[r * 4];
            float di = g_dinv[r];
            float e0 = __expf(lrelu(alc.x + ar4.x));
            float e1 = __expf(lrelu(alc.y + ar4.y));
            float e2 = __expf(lrelu(alc.z + ar4.z));
            float e3 = __expf(lrelu(alc.w + ar4.w));
            ps.x += e0; ps.y += e1; ps.z += e2; ps.w += e3;
            sw[wz][lane][0] = di * e0;
            sw[wz][lane][1] = di * e1;
            sw[wz][lane][2] = di * e2;
            sw[wz][lane][3] = di * e3;
            sr[wz][lane] = r;
        }
        __syncwarp();
        int cnt = min(32, end - t0);
#pragma unroll 4
        for (int u = 0; u < cnt; u++) {
            int r = sr[wz][u];
            float wh = sw[wz][u][h];
            uint2 u2 = *(const uint2*)&g_xt1[(size_t)r * 128 + lane * 4];
            float2 f0 = __half22float2(*(__half2*)&u2.x);
            float2 f1 = __half22float2(*(__half2*)&u2.y);
            acc.x += wh * f0.x; acc.y += wh * f0.y;
            acc.z += wh * f1.x; acc.w += wh * f1.y;
        }
        __syncwarp();
    }

#pragma unroll
    for (int d = 16; d > 0; d >>= 1) {
        ps.x += __shfl_xor_sync(0xffffffffu, ps.x, d);
        ps.y += __shfl_xor_sync(0xffffffffu, ps.y, d);
        ps.z += __shfl_xor_sync(0xffffffffu, ps.z, d);
        ps.w += __shfl_xor_sync(0xffffffffu, ps.w, d);
    }
    float se0 = __expf(lrelu(alc.x + arc.x));
    float se1 = __expf(lrelu(alc.y + arc.y));
    float se2 = __expf(lrelu(alc.z + arc.z));
    float se3 = __expf(lrelu(alc.w + arc.w));
    float rs0 = __fdividef(1.0f, ps.x + se0 + 1e-16f);
    float rs1 = __fdividef(1.0f, ps.y + se1 + 1e-16f);
    float rs2 = __fdividef(1.0f, ps.z + se2 + 1e-16f);
    float rs3 = __fdividef(1.0f, ps.w + se3 + 1e-16f);
    float seh = h < 2 ? (h == 0 ? se0 : se1) : (h == 2 ? se2 : se3);
    float rsh = h < 2 ? (h == 0 ? rs0 : rs1) : (h == 2 ? rs2 : rs3);

    uint2 uc = *(const uint2*)&g_xt1[(size_t)c * 128 + lane * 4];
    float2 c0 = __half22float2(*(__half2*)&uc.x);
    float2 c1 = __half22float2(*(__half2*)&uc.y);
    float wself = dc * seh;
    acc.x += wself * c0.x; acc.y += wself * c0.y;
    acc.z += wself * c1.x; acc.w += wself * c1.y;
    float sc = dc * rsh;

    float4 b = *(const float4*)&b1[lane * 4];
    float ox = fmaxf(acc.x * sc + b.x, 0.f);
    float oy = fmaxf(acc.y * sc + b.y, 0.f);
    float oz = fmaxf(acc.z * sc + b.z, 0.f);
    float ow = fmaxf(acc.w * sc + b.w, 0.f);
    uint2 st;
    *(__half2*)&st.x = __floats2half2_rn(ox, oy);
    *(__half2*)&st.y = __floats2half2_rn(oz, ow);
    *(uint2*)&g_h1[(size_t)c * 128 + lane * 4] = st;
}

// ---------------- GEMM2 (fp16 mma, zero-convert H) + fused alar2 epilogue ----------------
__global__ __launch_bounds__(256, 2) void k_gemm2(const float* __restrict__ W2,
                                                  const float* __restrict__ att, int n) {
    __shared__ __align__(16) __half Hs[128][56];
    __shared__ __half Ws2t[16][40];
    int tid = threadIdx.x, lane = tid & 31, wid = tid >> 5;
    int m0 = blockIdx.x * 128;
    int wm = wid * 16;

    float acc[2][4];
#pragma unroll
    for (int nt = 0; nt < 2; nt++)
#pragma unroll
        for (int q = 0; q < 4; q++) acc[nt][q] = 0.f;

    int lm = tid & 127;
    int lkq = (tid >> 7) * 16;
    int wkk = tid >> 3, wc = (tid & 7) * 2;

    for (int k0 = 0; k0 < 128; k0 += 32) {
        uint4 hv0 = make_uint4(0, 0, 0, 0), hv1 = hv0;
        if (m0 + lm < n) {
            const __half* hp = &g_h1[(size_t)(m0 + lm) * 128 + k0 + lkq];
            hv0 = *(const uint4*)hp;
            hv1 = *(const uint4*)(hp + 8);
        }
        *(uint4*)&Hs[lm][lkq] = hv0;
        *(uint4*)&Hs[lm][lkq + 8] = hv1;
        Ws2t[wc][wkk]     = __float2half_rn(W2[(size_t)(k0 + wkk) * 16 + wc]);
        Ws2t[wc + 1][wkk] = __float2half_rn(W2[(size_t)(k0 + wkk) * 16 + wc + 1]);
        __syncthreads();

        int gp = lane >> 2, tq2 = (lane & 3) * 2;
#pragma unroll
        for (int ks = 0; ks < 2; ks++) {
            int kb = ks * 16;
            uint32_t a[4];
            int r = wm + gp;
            a[0] = *(const uint32_t*)&Hs[r][kb + tq2];
            a[1] = *(const uint32_t*)&Hs[r + 8][kb + tq2];
            a[2] = *(const uint32_t*)&Hs[r][kb + tq2 + 8];
            a[3] = *(const uint32_t*)&Hs[r + 8][kb + tq2 + 8];
            uint32_t b0[2], b1[2];
            b0[0] = *(const uint32_t*)&Ws2t[gp][kb + tq2];
            b0[1] = *(const uint32_t*)&Ws2t[gp][kb + tq2 + 8];
            b1[0] = *(const uint32_t*)&Ws2t[8 + gp][kb + tq2];
            b1[1] = *(const uint32_t*)&Ws2t[8 + gp][kb + tq2 + 8];
            mma_f16(acc[0], a, b0);
            mma_f16(acc[1], a, b1);
        }
        __syncthreads();
    }

    int ar = lane >> 2, ac = (lane & 3) * 2;
#pragma unroll
    for (int nt = 0; nt < 2; nt++) {
        int r = m0 + wm + ar;
        int c = nt * 8 + ac;
        if (r < n)
            *(__half2*)&g_xt2[(size_t)r * 16 + c] = __floats2half2_rn(acc[nt][0], acc[nt][1]);
        if (r + 8 < n)
            *(__half2*)&g_xt2[(size_t)(r + 8) * 16 + c] = __floats2half2_rn(acc[nt][2], acc[nt][3]);
    }

    // ---- fused alar2 epilogue ----
    float wlv[4], wrv[4];
#pragma unroll
    for (int nt = 0; nt < 2; nt++) {
        int cc = nt * 8 + ac;
        wlv[nt * 2 + 0] = att[cc];
        wlv[nt * 2 + 1] = att[cc + 1];
        wrv[nt * 2 + 0] = att[16 + cc];
        wrv[nt * 2 + 1] = att[16 + cc + 1];
    }
    float alp0 = 0.f, arp0 = 0.f, alp1 = 0.f, arp1 = 0.f;
#pragma unroll
    for (int nt = 0; nt < 2; nt++) {
        alp0 += acc[nt][0] * wlv[nt * 2] + acc[nt][1] * wlv[nt * 2 + 1];
        arp0 += acc[nt][0] * wrv[nt * 2] + acc[nt][1] * wrv[nt * 2 + 1];
        alp1 += acc[nt][2] * wlv[nt * 2] + acc[nt][3] * wlv[nt * 2 + 1];
        arp1 += acc[nt][2] * wrv[nt * 2] + acc[nt][3] * wrv[nt * 2 + 1];
    }
#pragma unroll
    for (int d = 1; d <= 2; d <<= 1) {
        alp0 += __shfl_xor_sync(0xffffffffu, alp0, d);
        arp0 += __shfl_xor_sync(0xffffffffu, arp0, d);
        alp1 += __shfl_xor_sync(0xffffffffu, alp1, d);
        arp1 += __shfl_xor_sync(0xffffffffu, arp1, d);
    }
    if ((lane & 3) == 0) {
        int r = m0 + wm + ar;
        if (r < n)     { g_al2[r] = alp0;     g_ar2[r] = arp0; }
        if (r + 8 < n) { g_al2[r + 8] = alp1; g_ar2[r + 8] = arp1; }
    }
}

// ---------------- layer2 agg: half-warp per node, shfl staging ----------------
__global__ void k_agg2(const float* __restrict__ b2, int n, float* __restrict__ out) {
    int hw = (blockIdx.x * blockDim.x + threadIdx.x) >> 4;
    int sub = threadIdx.x & 15;
    unsigned hm = 0xFFFFu << (threadIdx.x & 16);
    bool valid = hw < n;
    int c = valid ? hw : (n - 1);
    float dc = g_dinv[c];
    float alc = g_al2[c];
    int beg = g_off[c], end = g_off[c + 1];

    float ps = 0.f, acc = 0.f;
    for (int t0 = beg; t0 < end; t0 += 16) {
        int j = t0 + sub;
        int r = 0; float wv = 0.f;
        if (j < end) {
            r = __ldg(&g_adj[j]);
            float e = __expf(lrelu(alc + g_ar2[r]));
            ps += e;
            wv = g_dinv[r] * e;
        }
        int cnt = min(16, end - t0);
        for (int u = 0; u < cnt; u++) {
            int ru = __shfl_sync(hm, r, u, 16);
            float wu = __shfl_sync(hm, wv, u, 16);
            acc += wu * __half2float(g_xt2[(size_t)ru * 16 + sub]);
        }
    }
#pragma unroll
    for (int d = 8; d > 0; d >>= 1)
        ps += __shfl_xor_sync(hm, ps, d, 16);
    float se = __expf(lrelu(alc + g_ar2[c]));
    float rs = __fdividef(1.0f, ps + se + 1e-16f);
    acc += dc * se * __half2float(g_xt2[(size_t)c * 16 + sub]);
    if (valid) out[(size_t)c * 16 + sub] = dc * rs * acc + b2[sub];
}

// ---------------- launch (stream-forked; gemm1 at submission index 3 for ncu) ----------------
extern "C" void kernel_launch(void* const* d_in, const int* in_sizes, int n_in,
                              void* d_out, int out_size) {
    const float* x    = (const float*)d_in[0];
    const int*   ei   = (const int*)d_in[1];
    const float* W1   = (const float*)d_in[2];
    const float* att1 = (const float*)d_in[3];
    const float* b1   = (const float*)d_in[4];
    const float* W2   = (const float*)d_in[5];
    const float* att2 = (const float*)d_in[6];
    const float* b2   = (const float*)d_in[7];
    float* out = (float*)d_out;

    int n = in_sizes[0] / 256;
    int e = in_sizes[1] / 2;
    int nb = (n + 1023) / 1024;
    const int T = 256;

    cudaStream_t s2;
    cudaEvent_t evFork, evJoin;
    cudaStreamCreateWithFlags(&s2, cudaStreamNonBlocking);
    cudaEventCreateWithFlags(&evFork, cudaEventDisableTiming);
    cudaEventCreateWithFlags(&evJoin, cudaEventDisableTiming);

    cudaEventRecord(evFork, 0);
    cudaStreamWaitEvent(s2, evFork, 0);

    // chain A (side stream) begins
    k_init<<<(n + T - 1) / T, T, 0, s2>>>(n);                 // idx 0
    k_deg_count<<<(e + T - 1) / T, T, 0, s2>>>(ei, e);        // idx 1
    k_scan_blocks<<<nb, 1024, 0, s2>>>(n);                    // idx 2
    // chain B (main stream) — submitted at idx 3 so ncu profiles it
    k_gemm1<<<(n + 127) / 128, 256>>>(x, W1, att1, n);        // idx 3
    // chain A continues
    k_scan_add<<<nb, 1024, 0, s2>>>(n, e);                    // idx 4
    k_scatter<<<(e + T - 1) / T, T, 0, s2>>>(ei, e);          // idx 5
    cudaEventRecord(evJoin, s2);

    // join: aggregation needs both chains
    cudaStreamWaitEvent(0, evJoin, 0);
    k_agg1<<<(n * 32 + 255) / 256, 256>>>(b1, n);

    k_gemm2<<<(n + 127) / 128, 256>>>(W2, att2, n);
    k_agg2<<<(n * 16 + 255) / 256, 256>>>(b2, n, out);
}

// round 15
// speedup vs baseline: 1.1415x; 1.0242x over previous
#include <cuda_runtime.h>
#include <cuda_fp16.h>
#include <math.h>
#include <stdint.h>

#define NN 100000
#define EE 1600000
#define NB_SCAN ((NN + 1023) / 1024)

// ---------------- scratch (static device globals) ----------------
__device__ float    g_deg[NN];
__device__ float    g_dinv[NN];
__device__ __half   g_xt1[(size_t)NN * 128];
__device__ float    g_al1[NN * 4];
__device__ float    g_ar1[NN * 4];
__device__ __half   g_h1[(size_t)NN * 128];
__device__ __half   g_xt2[NN * 16];
__device__ float    g_al2[NN];
__device__ float    g_ar2[NN];
__device__ uint32_t g_w1h[128 * 128];   // W1 pre-paired fp16: [k2][n] = (W[2k2][n], W[2k2+1][n])
// CSR by destination (col)
__device__ int      g_cnt[NN];
__device__ int      g_off[NN + 1];
__device__ int      g_wpos[NN];
__device__ int      g_bsum[NB_SCAN + 1];
__device__ int      g_adj[EE];     // source row only

__device__ __forceinline__ float lrelu(float a) { return a >= 0.f ? a : 0.2f * a; }

__device__ __forceinline__ uint32_t packh2(float x, float y) {
    __half2 h = __floats2half2_rn(x, y);
    return *(uint32_t*)&h;
}

__device__ __forceinline__ void mma_f16(float* c, const uint32_t* a, const uint32_t* b) {
    asm volatile(
        "mma.sync.aligned.m16n8k16.row.col.f32.f16.f16.f32 "
        "{%0,%1,%2,%3}, {%4,%5,%6,%7}, {%8,%9}, {%0,%1,%2,%3};"
        : "+f"(c[0]), "+f"(c[1]), "+f"(c[2]), "+f"(c[3])
        : "r"(a[0]), "r"(a[1]), "r"(a[2]), "r"(a[3]), "r"(b[0]), "r"(b[1]));
}

__device__ __forceinline__ void ldsm4(uint32_t* a, uint32_t addr) {
    asm volatile("ldmatrix.sync.aligned.m8n8.x4.shared.b16 {%0,%1,%2,%3}, [%4];"
                 : "=r"(a[0]), "=r"(a[1]), "=r"(a[2]), "=r"(a[3]) : "r"(addr));
}

__device__ __forceinline__ void cp16(uint32_t d, const void* s, int sz) {
    asm volatile("cp.async.ca.shared.global [%0], [%1], 16, %2;"
                 :: "r"(d), "l"(s), "r"(sz));
}
__device__ __forceinline__ void cp_commit() {
    asm volatile("cp.async.commit_group;" ::: "memory");
}

// ---------------- init ----------------
__global__ void k_init(int n) {
    int i = blockIdx.x * blockDim.x + threadIdx.x;
    if (i < n) { g_deg[i] = 1.0f; g_cnt[i] = 0; }
}

__global__ void k_deg_count(const int* __restrict__ ei, int e) {
    int i = blockIdx.x * blockDim.x + threadIdx.x;
    if (i < e) {
        atomicAdd(&g_deg[ei[i]], 1.0f);
        atomicAdd(&g_cnt[ei[e + i]], 1);
    }
}

// ---------------- W1 -> paired fp16 ----------------
__global__ void k_convw(const float* __restrict__ W) {
    int i = blockIdx.x * blockDim.x + threadIdx.x;
    if (i < 128 * 128) {
        int k2 = i >> 7, nn = i & 127;
        g_w1h[i] = packh2(W[(size_t)(2 * k2) * 128 + nn], W[(size_t)(2 * k2 + 1) * 128 + nn]);
    }
}

// ---------------- multi-block exclusive scan over g_cnt (+ fused dinv) ----------------
__global__ void k_scan_blocks(int n) {
    __shared__ int warpsums[32];
    int i = blockIdx.x * 1024 + threadIdx.x;
    int lane = threadIdx.x & 31, wid = threadIdx.x >> 5;
    if (i < n) g_dinv[i] = rsqrtf(g_deg[i]);
    int v = (i < n) ? g_cnt[i] : 0;
    int s = v;
#pragma unroll
    for (int d = 1; d < 32; d <<= 1) {
        int t = __shfl_up_sync(0xffffffffu, s, d);
        if (lane >= d) s += t;
    }
    if (lane == 31) warpsums[wid] = s;
    __syncthreads();
    if (wid == 0) {
        int ws = warpsums[lane];
#pragma unroll
        for (int d = 1; d < 32; d <<= 1) {
            int t = __shfl_up_sync(0xffffffffu, ws, d);
            if (lane >= d) ws += t;
        }
        warpsums[lane] = ws;
    }
    __syncthreads();
    int base = (wid > 0) ? warpsums[wid - 1] : 0;
    int exc = s - v + base;
    if (i < n) g_off[i] = exc;
    if (threadIdx.x == 1023) g_bsum[blockIdx.x] = exc + v;
}

__global__ void k_scan_add(int n, int e) {
    __shared__ int sbase;
    if (threadIdx.x == 0) sbase = 0;
    __syncthreads();
    if (threadIdx.x < blockIdx.x) atomicAdd(&sbase, g_bsum[threadIdx.x]);
    __syncthreads();
    int i = blockIdx.x * 1024 + threadIdx.x;
    if (i < n) {
        int o = g_off[i] + sbase;
        g_off[i] = o;
        g_wpos[i] = o;
    }
    if (i == 0) g_off[n] = e;
}

__global__ void k_scatter(const int* __restrict__ ei, int e) {
    int i = blockIdx.x * blockDim.x + threadIdx.x;
    if (i >= e) return;
    int r = ei[i], c = ei[e + i];
    int p = atomicAdd(&g_wpos[c], 1);
    g_adj[p] = r;
}

// ---------------- GEMM1: fp16 smem, cp.async W, ldmatrix A, one sync/tile ----------------
__global__ __launch_bounds__(256, 2) void k_gemm1(const float* __restrict__ X,
                                                  const float* __restrict__ att, int n) {
    __shared__ __align__(16) __half   Xs[2][128][40];    // [m][k:32 + pad:8]
    __shared__ __align__(16) uint32_t Wsp[2][16][136];   // [k2][n:128 + pad:8]
    int tid = threadIdx.x, lane = tid & 31, wid = tid >> 5;
    int m0 = blockIdx.x * 128;
    int wm = (wid & 1) * 64, wn = (wid >> 1) * 32;

    float acc[4][4][4];
#pragma unroll
    for (int mt = 0; mt < 4; mt++)
#pragma unroll
        for (int nt = 0; nt < 4; nt++)
#pragma unroll
            for (int q = 0; q < 4; q++) acc[mt][nt][q] = 0.f;

    // X copy role: row lm, 16 k-values at ks
    int lm = tid & 127, ks = (tid >> 7) * 16;
    // W cp.async role: k2-row (0..15), 8 n-words at n0
    int k2 = tid >> 4, n0 = (tid & 15) * 8;
    bool mok = (m0 + lm < n);
    const float* xp = X + (size_t)(m0 + lm) * 256 + ks;
    const uint32_t* wsrc0 = g_w1h + k2 * 128 + n0;
    uint32_t wdst = (uint32_t)__cvta_generic_to_shared(&Wsp[0][k2][n0]);
    const uint32_t WST = sizeof(uint32_t) * 16 * 136;

    float4 xv[4];
#pragma unroll
    for (int j = 0; j < 4; j++)
        xv[j] = mok ? *(const float4*)(xp + j * 4) : make_float4(0.f, 0.f, 0.f, 0.f);
    cp16(wdst, wsrc0, 16);
    cp16(wdst + 16, wsrc0 + 4, 16);
    cp_commit();

    int gp = lane >> 2, q = lane & 3;
    // ldmatrix lane mapping for A (m16k16 = 4x m8k8)
    int arow = wm + (lane & 7) + ((lane >> 3) & 1) * 8;
    int akoff = (lane >> 4) * 8;

#pragma unroll 1
    for (int t = 0; t < 8; t++) {
        int s = t & 1;
        // store X tile (pack to fp16)
#pragma unroll
        for (int j = 0; j < 4; j++) {
            uint2 u;
            u.x = packh2(xv[j].x, xv[j].y);
            u.y = packh2(xv[j].z, xv[j].w);
            *(uint2*)&Xs[s][lm][ks + j * 4] = u;
        }
        __syncthreads();   // all warps done mma(t-1); stores above visible

        if (t < 7) {
            // W for tile t+1 into the other stage (safe: mma(t-1) readers done)
            const uint32_t* wsn = wsrc0 + (size_t)(t + 1) * 16 * 128;
            uint32_t wd1 = wdst + ((t + 1) & 1) * WST;
            cp16(wd1, wsn, 16);
            cp16(wd1 + 16, wsn + 4, 16);
            cp_commit();
            asm volatile("cp.async.wait_group 1;" ::: "memory");  // W(t) arrived
            // prefetch X regs for t+1
            int kn = (t + 1) * 32;
#pragma unroll
            for (int j = 0; j < 4; j++)
                xv[j] = mok ? *(const float4*)(xp + kn + j * 4) : make_float4(0.f, 0.f, 0.f, 0.f);
        } else {
            asm volatile("cp.async.wait_group 0;" ::: "memory");
        }

        uint32_t xbase = (uint32_t)__cvta_generic_to_shared(&Xs[s][0][0]);
#pragma unroll
        for (int ks2 = 0; ks2 < 2; ks2++) {
            int kb = ks2 * 16;
            uint32_t a[4][4], b[4][2];
#pragma unroll
            for (int mt = 0; mt < 4; mt++) {
                uint32_t addr = xbase + (uint32_t)(((arow + mt * 16) * 40 + kb + akoff) * 2);
                ldsm4(a[mt], addr);
            }
#pragma unroll
            for (int nt = 0; nt < 4; nt++) {
                int c = wn + nt * 8 + gp;
                b[nt][0] = Wsp[s][kb / 2 + q][c];
                b[nt][1] = Wsp[s][kb / 2 + q + 4][c];
            }
#pragma unroll
            for (int mt = 0; mt < 4; mt++)
#pragma unroll
                for (int nt = 0; nt < 4; nt++)
                    mma_f16(acc[mt][nt], a[mt], b[nt]);
        }
    }

    int ar = lane >> 2, ac = (lane & 3) * 2;
#pragma unroll
    for (int mt = 0; mt < 4; mt++) {
        int r = m0 + wm + mt * 16 + ar;
#pragma unroll
        for (int nt = 0; nt < 4; nt++) {
            int c = wn + nt * 8 + ac;
            if (r < n)
                *(__half2*)&g_xt1[(size_t)r * 128 + c] =
                    __floats2half2_rn(acc[mt][nt][0], acc[mt][nt][1]);
            if (r + 8 < n)
                *(__half2*)&g_xt1[(size_t)(r + 8) * 128 + c] =
                    __floats2half2_rn(acc[mt][nt][2], acc[mt][nt][3]);
        }
    }

    // ---- fused alar1 epilogue ----
    int hh = wid >> 1;
    float wlv[8], wrv[8];
#pragma unroll
    for (int nt = 0; nt < 4; nt++) {
        int cc = nt * 8 + ac;
        wlv[nt * 2 + 0] = att[hh * 64 + cc];
        wlv[nt * 2 + 1] = att[hh * 64 + cc + 1];
        wrv[nt * 2 + 0] = att[hh * 64 + 32 + cc];
        wrv[nt * 2 + 1] = att[hh * 64 + 32 + cc + 1];
    }
#pragma unroll
    for (int mt = 0; mt < 4; mt++) {
        float alp0 = 0.f, arp0 = 0.f, alp1 = 0.f, arp1 = 0.f;
#pragma unroll
        for (int nt = 0; nt < 4; nt++) {
            alp0 += acc[mt][nt][0] * wlv[nt * 2] + acc[mt][nt][1] * wlv[nt * 2 + 1];
            arp0 += acc[mt][nt][0] * wrv[nt * 2] + acc[mt][nt][1] * wrv[nt * 2 + 1];
            alp1 += acc[mt][nt][2] * wlv[nt * 2] + acc[mt][nt][3] * wlv[nt * 2 + 1];
            arp1 += acc[mt][nt][2] * wrv[nt * 2] + acc[mt][nt][3] * wrv[nt * 2 + 1];
        }
#pragma unroll
        for (int d = 1; d <= 2; d <<= 1) {
            alp0 += __shfl_xor_sync(0xffffffffu, alp0, d);
            arp0 += __shfl_xor_sync(0xffffffffu, arp0, d);
            alp1 += __shfl_xor_sync(0xffffffffu, alp1, d);
            arp1 += __shfl_xor_sync(0xffffffffu, arp1, d);
        }
        if ((lane & 3) == 0) {
            int r = m0 + wm + mt * 16 + ar;
            if (r < n)     { g_al1[r * 4 + hh] = alp0;       g_ar1[r * 4 + hh] = arp0; }
            if (r + 8 < n) { g_al1[(r + 8) * 4 + hh] = alp1; g_ar1[(r + 8) * 4 + hh] = arp1; }
        }
    }
}

// ---------------- single-sweep fused softmax + aggregation layer1 (fp16 gathers) ----------------
__global__ void k_agg1(const float* __restrict__ b1, int n) {
    __shared__ float sw[8][32][4];
    __shared__ int   sr[8][32];
    int w = (blockIdx.x * blockDim.x + threadIdx.x) >> 5;
    if (w >= n) return;
    int lane = threadIdx.x & 31;
    int wz = (threadIdx.x >> 5) & 7;
    int c = w;
    float dc = g_dinv[c];
    float4 alc = *(const float4*)&g_al1[c * 4];
    float4 arc = *(const float4*)&g_ar1[c * 4];
    int beg = g_off[c], end = g_off[c + 1];
    int h = lane >> 3;

    float4 ps = make_float4(0.f, 0.f, 0.f, 0.f);
    float4 acc = make_float4(0.f, 0.f, 0.f, 0.f);

    for (int t0 = beg; t0 < end; t0 += 32) {
        int j = t0 + lane;
        if (j < end) {
            int r = __ldg(&g_adj[j]);
            float4 ar4 = *(const float4*)&g_ar1[r * 4];
            float di = g_dinv[r];
            float e0 = __expf(lrelu(alc.x + ar4.x));
            float e1 = __expf(lrelu(alc.y + ar4.y));
            float e2 = __expf(lrelu(alc.z + ar4.z));
            float e3 = __expf(lrelu(alc.w + ar4.w));
            ps.x += e0; ps.y += e1; ps.z += e2; ps.w += e3;
            sw[wz][lane][0] = di * e0;
            sw[wz][lane][1] = di * e1;
            sw[wz][lane][2] = di * e2;
            sw[wz][lane][3] = di * e3;
            sr[wz][lane] = r;
        }
        __syncwarp();
        int cnt = min(32, end - t0);
#pragma unroll 4
        for (int u = 0; u < cnt; u++) {
            int r = sr[wz][u];
            float wh = sw[wz][u][h];
            uint2 u2 = *(const uint2*)&g_xt1[(size_t)r * 128 + lane * 4];
            float2 f0 = __half22float2(*(__half2*)&u2.x);
            float2 f1 = __half22float2(*(__half2*)&u2.y);
            acc.x += wh * f0.x; acc.y += wh * f0.y;
            acc.z += wh * f1.x; acc.w += wh * f1.y;
        }
        __syncwarp();
    }

#pragma unroll
    for (int d = 16; d > 0; d >>= 1) {
        ps.x += __shfl_xor_sync(0xffffffffu, ps.x, d);
        ps.y += __shfl_xor_sync(0xffffffffu, ps.y, d);
        ps.z += __shfl_xor_sync(0xffffffffu, ps.z, d);
        ps.w += __shfl_xor_sync(0xffffffffu, ps.w, d);
    }
    float se0 = __expf(lrelu(alc.x + arc.x));
    float se1 = __expf(lrelu(alc.y + arc.y));
    float se2 = __expf(lrelu(alc.z + arc.z));
    float se3 = __expf(lrelu(alc.w + arc.w));
    float rs0 = __fdividef(1.0f, ps.x + se0 + 1e-16f);
    float rs1 = __fdividef(1.0f, ps.y + se1 + 1e-16f);
    float rs2 = __fdividef(1.0f, ps.z + se2 + 1e-16f);
    float rs3 = __fdividef(1.0f, ps.w + se3 + 1e-16f);
    float seh = h < 2 ? (h == 0 ? se0 : se1) : (h == 2 ? se2 : se3);
    float rsh = h < 2 ? (h == 0 ? rs0 : rs1) : (h == 2 ? rs2 : rs3);

    uint2 uc = *(const uint2*)&g_xt1[(size_t)c * 128 + lane * 4];
    float2 c0 = __half22float2(*(__half2*)&uc.x);
    float2 c1 = __half22float2(*(__half2*)&uc.y);
    float wself = dc * seh;
    acc.x += wself * c0.x; acc.y += wself * c0.y;
    acc.z += wself * c1.x; acc.w += wself * c1.y;
    float sc = dc * rsh;

    float4 b = *(const float4*)&b1[lane * 4];
    float ox = fmaxf(acc.x * sc + b.x, 0.f);
    float oy = fmaxf(acc.y * sc + b.y, 0.f);
    float oz = fmaxf(acc.z * sc + b.z, 0.f);
    float ow = fmaxf(acc.w * sc + b.w, 0.f);
    uint2 st;
    *(__half2*)&st.x = __floats2half2_rn(ox, oy);
    *(__half2*)&st.y = __floats2half2_rn(oz, ow);
    *(uint2*)&g_h1[(size_t)c * 128 + lane * 4] = st;
}

// ---------------- GEMM2 (fp16 mma, zero-convert H) + fused alar2 epilogue ----------------
__global__ __launch_bounds__(256, 2) void k_gemm2(const float* __restrict__ W2,
                                                  const float* __restrict__ att, int n) {
    __shared__ __align__(16) __half Hs[128][56];
    __shared__ __half Ws2t[16][40];
    int tid = threadIdx.x, lane = tid & 31, wid = tid >> 5;
    int m0 = blockIdx.x * 128;
    int wm = wid * 16;

    float acc[2][4];
#pragma unroll
    for (int nt = 0; nt < 2; nt++)
#pragma unroll
        for (int q = 0; q < 4; q++) acc[nt][q] = 0.f;

    int lm = tid & 127;
    int lkq = (tid >> 7) * 16;
    int wkk = tid >> 3, wc = (tid & 7) * 2;

    for (int k0 = 0; k0 < 128; k0 += 32) {
        uint4 hv0 = make_uint4(0, 0, 0, 0), hv1 = hv0;
        if (m0 + lm < n) {
            const __half* hp = &g_h1[(size_t)(m0 + lm) * 128 + k0 + lkq];
            hv0 = *(const uint4*)hp;
            hv1 = *(const uint4*)(hp + 8);
        }
        *(uint4*)&Hs[lm][lkq] = hv0;
        *(uint4*)&Hs[lm][lkq + 8] = hv1;
        Ws2t[wc][wkk]     = __float2half_rn(W2[(size_t)(k0 + wkk) * 16 + wc]);
        Ws2t[wc + 1][wkk] = __float2half_rn(W2[(size_t)(k0 + wkk) * 16 + wc + 1]);
        __syncthreads();

        int gp = lane >> 2, tq2 = (lane & 3) * 2;
#pragma unroll
        for (int ks = 0; ks < 2; ks++) {
            int kb = ks * 16;
            uint32_t a[4];
            int r = wm + gp;
            a[0] = *(const uint32_t*)&Hs[r][kb + tq2];
            a[1] = *(const uint32_t*)&Hs[r + 8][kb + tq2];
            a[2] = *(const uint32_t*)&Hs[r][kb + tq2 + 8];
            a[3] = *(const uint32_t*)&Hs[r + 8][kb + tq2 + 8];
            uint32_t b0[2], b1[2];
            b0[0] = *(const uint32_t*)&Ws2t[gp][kb + tq2];
            b0[1] = *(const uint32_t*)&Ws2t[gp][kb + tq2 + 8];
            b1[0] = *(const uint32_t*)&Ws2t[8 + gp][kb + tq2];
            b1[1] = *(const uint32_t*)&Ws2t[8 + gp][kb + tq2 + 8];
            mma_f16(acc[0], a, b0);
            mma_f16(acc[1], a, b1);
        }
        __syncthreads();
    }

    int ar = lane >> 2, ac = (lane & 3) * 2;
#pragma unroll
    for (int nt = 0; nt < 2; nt++) {
        int r = m0 + wm + ar;
        int c = nt * 8 + ac;
        if (r < n)
            *(__half2*)&g_xt2[(size_t)r * 16 + c] = __floats2half2_rn(acc[nt][0], acc[nt][1]);
        if (r + 8 < n)
            *(__half2*)&g_xt2[(size_t)(r + 8) * 16 + c] = __floats2half2_rn(acc[nt][2], acc[nt][3]);
    }

    // ---- fused alar2 epilogue ----
    float wlv[4], wrv[4];
#pragma unroll
    for (int nt = 0; nt < 2; nt++) {
        int cc = nt * 8 + ac;
        wlv[nt * 2 + 0] = att[cc];
        wlv[nt * 2 + 1] = att[cc + 1];
        wrv[nt * 2 + 0] = att[16 + cc];
        wrv[nt * 2 + 1] = att[16 + cc + 1];
    }
    float alp0 = 0.f, arp0 = 0.f, alp1 = 0.f, arp1 = 0.f;
#pragma unroll
    for (int nt = 0; nt < 2; nt++) {
        alp0 += acc[nt][0] * wlv[nt * 2] + acc[nt][1] * wlv[nt * 2 + 1];
        arp0 += acc[nt][0] * wrv[nt * 2] + acc[nt][1] * wrv[nt * 2 + 1];
        alp1 += acc[nt][2] * wlv[nt * 2] + acc[nt][3] * wlv[nt * 2 + 1];
        arp1 += acc[nt][2] * wrv[nt * 2] + acc[nt][3] * wrv[nt * 2 + 1];
    }
#pragma unroll
    for (int d = 1; d <= 2; d <<= 1) {
        alp0 += __shfl_xor_sync(0xffffffffu, alp0, d);
        arp0 += __shfl_xor_sync(0xffffffffu, arp0, d);
        alp1 += __shfl_xor_sync(0xffffffffu, alp1, d);
        arp1 += __shfl_xor_sync(0xffffffffu, arp1, d);
    }
    if ((lane & 3) == 0) {
        int r = m0 + wm + ar;
        if (r < n)     { g_al2[r] = alp0;     g_ar2[r] = arp0; }
        if (r + 8 < n) { g_al2[r + 8] = alp1; g_ar2[r + 8] = arp1; }
    }
}

// ---------------- layer2 agg: half-warp per node, shfl staging ----------------
__global__ void k_agg2(const float* __restrict__ b2, int n, float* __restrict__ out) {
    int hw = (blockIdx.x * blockDim.x + threadIdx.x) >> 4;
    int sub = threadIdx.x & 15;
    unsigned hm = 0xFFFFu << (threadIdx.x & 16);
    bool valid = hw < n;
    int c = valid ? hw : (n - 1);
    float dc = g_dinv[c];
    float alc = g_al2[c];
    int beg = g_off[c], end = g_off[c + 1];

    float ps = 0.f, acc = 0.f;
    for (int t0 = beg; t0 < end; t0 += 16) {
        int j = t0 + sub;
        int r = 0; float wv = 0.f;
        if (j < end) {
            r = __ldg(&g_adj[j]);
            float e = __expf(lrelu(alc + g_ar2[r]));
            ps += e;
            wv = g_dinv[r] * e;
        }
        int cnt = min(16, end - t0);
        for (int u = 0; u < cnt; u++) {
            int ru = __shfl_sync(hm, r, u, 16);
            float wu = __shfl_sync(hm, wv, u, 16);
            acc += wu * __half2float(g_xt2[(size_t)ru * 16 + sub]);
        }
    }
#pragma unroll
    for (int d = 8; d > 0; d >>= 1)
        ps += __shfl_xor_sync(hm, ps, d, 16);
    float se = __expf(lrelu(alc + g_ar2[c]));
    float rs = __fdividef(1.0f, ps + se + 1e-16f);
    acc += dc * se * __half2float(g_xt2[(size_t)c * 16 + sub]);
    if (valid) out[(size_t)c * 16 + sub] = dc * rs * acc + b2[sub];
}

// ---------------- launch (stream-forked; gemm1 at submission index 3 for ncu) ----------------
extern "C" void kernel_launch(void* const* d_in, const int* in_sizes, int n_in,
                              void* d_out, int out_size) {
    const float* x    = (const float*)d_in[0];
    const int*   ei   = (const int*)d_in[1];
    const float* W1   = (const float*)d_in[2];
    const float* att1 = (const float*)d_in[3];
    const float* b1   = (const float*)d_in[4];
    const float* W2   = (const float*)d_in[5];
    const float* att2 = (const float*)d_in[6];
    const float* b2   = (const float*)d_in[7];
    float* out = (float*)d_out;

    int n = in_sizes[0] / 256;
    int e = in_sizes[1] / 2;
    int nb = (n + 1023) / 1024;
    const int T = 256;

    cudaStream_t s2;
    cudaEvent_t evFork, evJoin;
    cudaStreamCreateWithFlags(&s2, cudaStreamNonBlocking);
    cudaEventCreateWithFlags(&evFork, cudaEventDisableTiming);
    cudaEventCreateWithFlags(&evJoin, cudaEventDisableTiming);

    cudaEventRecord(evFork, 0);
    cudaStreamWaitEvent(s2, evFork, 0);

    // chain A (side stream) begins
    k_init<<<(n + T - 1) / T, T, 0, s2>>>(n);                 // idx 0
    k_deg_count<<<(e + T - 1) / T, T, 0, s2>>>(ei, e);        // idx 1
    // main stream: W convert then gemm1 (gemm1 at idx 3 for ncu)
    k_convw<<<64, 256>>>(W1);                                 // idx 2
    k_gemm1<<<(n + 127) / 128, 256>>>(x, att1, n);            // idx 3
    // chain A continues
    k_scan_blocks<<<nb, 1024, 0, s2>>>(n);                    // idx 4
    k_scan_add<<<nb, 1024, 0, s2>>>(n, e);                    // idx 5
    k_scatter<<<(e + T - 1) / T, T, 0, s2>>>(ei, e);          // idx 6
    cudaEventRecord(evJoin, s2);

    // join: aggregation needs both chains
    cudaStreamWaitEvent(0, evJoin, 0);
    k_agg1<<<(n * 32 + 255) / 256, 256>>>(b1, n);

    k_gemm2<<<(n + 127) / 128, 256>>>(W2, att2, n);
    k_agg2<<<(n * 16 + 255) / 256, 256>>>(b2, n, out);
}

// round 16
// speedup vs baseline: 1.1678x; 1.0230x over previous
#include <cuda_runtime.h>
#include <cuda_fp16.h>
#include <math.h>
#include <stdint.h>

#define NN 100000
#define EE 1600000
#define NB_SCAN ((NN + 1023) / 1024)

// ---------------- scratch (static device globals) ----------------
__device__ float    g_deg[NN];
__device__ float    g_dinv[NN];
__device__ __half   g_xt1[(size_t)NN * 128];
__device__ float    g_al1[NN * 4];
__device__ float    g_ar1[NN * 4];
__device__ __half   g_h1[(size_t)NN * 128];
__device__ __half   g_xt2[NN * 16];
__device__ float    g_al2[NN];
__device__ float    g_ar2[NN];
__device__ uint32_t g_w1h[128 * 128];   // W1 pre-paired fp16: [k2][n] = (W[2k2][n], W[2k2+1][n])
// CSR by destination (col)
__device__ int      g_cnt[NN];
__device__ int      g_off[NN + 1];
__device__ int      g_wpos[NN];
__device__ int      g_bsum[NB_SCAN + 1];
__device__ int      g_adj[EE];     // source row only

__device__ __forceinline__ float lrelu(float a) { return a >= 0.f ? a : 0.2f * a; }

__device__ __forceinline__ uint32_t packh2(float x, float y) {
    __half2 h = __floats2half2_rn(x, y);
    return *(uint32_t*)&h;
}

__device__ __forceinline__ void mma_f16(float* c, const uint32_t* a, const uint32_t* b) {
    asm volatile(
        "mma.sync.aligned.m16n8k16.row.col.f32.f16.f16.f32 "
        "{%0,%1,%2,%3}, {%4,%5,%6,%7}, {%8,%9}, {%0,%1,%2,%3};"
        : "+f"(c[0]), "+f"(c[1]), "+f"(c[2]), "+f"(c[3])
        : "r"(a[0]), "r"(a[1]), "r"(a[2]), "r"(a[3]), "r"(b[0]), "r"(b[1]));
}

__device__ __forceinline__ void ldsm4(uint32_t* a, uint32_t addr) {
    asm volatile("ldmatrix.sync.aligned.m8n8.x4.shared.b16 {%0,%1,%2,%3}, [%4];"
                 : "=r"(a[0]), "=r"(a[1]), "=r"(a[2]), "=r"(a[3]) : "r"(addr));
}

__device__ __forceinline__ void cp16(uint32_t d, const void* s, int sz) {
    asm volatile("cp.async.ca.shared.global [%0], [%1], 16, %2;"
                 :: "r"(d), "l"(s), "r"(sz));
}
__device__ __forceinline__ void cp_commit() {
    asm volatile("cp.async.commit_group;" ::: "memory");
}

// ---------------- init ----------------
__global__ void k_init(int n) {
    int i = blockIdx.x * blockDim.x + threadIdx.x;
    if (i < n) { g_deg[i] = 1.0f; g_cnt[i] = 0; }
}

__global__ void k_deg_count(const int* __restrict__ ei, int e) {
    int i = blockIdx.x * blockDim.x + threadIdx.x;
    if (i < e) {
        atomicAdd(&g_deg[ei[i]], 1.0f);
        atomicAdd(&g_cnt[ei[e + i]], 1);
    }
}

// ---------------- W1 -> paired fp16 ----------------
__global__ void k_convw(const float* __restrict__ W) {
    int i = blockIdx.x * blockDim.x + threadIdx.x;
    if (i < 128 * 128) {
        int k2 = i >> 7, nn = i & 127;
        g_w1h[i] = packh2(W[(size_t)(2 * k2) * 128 + nn], W[(size_t)(2 * k2 + 1) * 128 + nn]);
    }
}

// ---------------- multi-block exclusive scan over g_cnt (+ fused dinv) ----------------
__global__ void k_scan_blocks(int n) {
    __shared__ int warpsums[32];
    int i = blockIdx.x * 1024 + threadIdx.x;
    int lane = threadIdx.x & 31, wid = threadIdx.x >> 5;
    if (i < n) g_dinv[i] = rsqrtf(g_deg[i]);
    int v = (i < n) ? g_cnt[i] : 0;
    int s = v;
#pragma unroll
    for (int d = 1; d < 32; d <<= 1) {
        int t = __shfl_up_sync(0xffffffffu, s, d);
        if (lane >= d) s += t;
    }
    if (lane == 31) warpsums[wid] = s;
    __syncthreads();
    if (wid == 0) {
        int ws = warpsums[lane];
#pragma unroll
        for (int d = 1; d < 32; d <<= 1) {
            int t = __shfl_up_sync(0xffffffffu, ws, d);
            if (lane >= d) ws += t;
        }
        warpsums[lane] = ws;
    }
    __syncthreads();
    int base = (wid > 0) ? warpsums[wid - 1] : 0;
    int exc = s - v + base;
    if (i < n) g_off[i] = exc;
    if (threadIdx.x == 1023) g_bsum[blockIdx.x] = exc + v;
}

__global__ void k_scan_add(int n, int e) {
    __shared__ int sbase;
    if (threadIdx.x == 0) sbase = 0;
    __syncthreads();
    if (threadIdx.x < blockIdx.x) atomicAdd(&sbase, g_bsum[threadIdx.x]);
    __syncthreads();
    int i = blockIdx.x * 1024 + threadIdx.x;
    if (i < n) {
        int o = g_off[i] + sbase;
        g_off[i] = o;
        g_wpos[i] = o;
    }
    if (i == 0) g_off[n] = e;
}

__global__ void k_scatter(const int* __restrict__ ei, int e) {
    int i = blockIdx.x * blockDim.x + threadIdx.x;
    if (i >= e) return;
    int r = ei[i], c = ei[e + i];
    int p = atomicAdd(&g_wpos[c], 1);
    g_adj[p] = r;
}

// ---------------- GEMM1: fp16 smem, cp.async W, ldmatrix A, one sync/tile ----------------
__global__ __launch_bounds__(256, 2) void k_gemm1(const float* __restrict__ X,
                                                  const float* __restrict__ att, int n) {
    __shared__ __align__(16) __half   Xs[2][128][40];    // [m][k:32 + pad:8]
    __shared__ __align__(16) uint32_t Wsp[2][16][136];   // [k2][n:128 + pad:8]
    int tid = threadIdx.x, lane = tid & 31, wid = tid >> 5;
    int m0 = blockIdx.x * 128;
    int wm = (wid & 1) * 64, wn = (wid >> 1) * 32;

    float acc[4][4][4];
#pragma unroll
    for (int mt = 0; mt < 4; mt++)
#pragma unroll
        for (int nt = 0; nt < 4; nt++)
#pragma unroll
            for (int q = 0; q < 4; q++) acc[mt][nt][q] = 0.f;

    int lm = tid & 127, ks = (tid >> 7) * 16;
    int k2 = tid >> 4, n0 = (tid & 15) * 8;
    bool mok = (m0 + lm < n);
    const float* xp = X + (size_t)(m0 + lm) * 256 + ks;
    const uint32_t* wsrc0 = g_w1h + k2 * 128 + n0;
    uint32_t wdst = (uint32_t)__cvta_generic_to_shared(&Wsp[0][k2][n0]);
    const uint32_t WST = sizeof(uint32_t) * 16 * 136;

    float4 xv[4];
#pragma unroll
    for (int j = 0; j < 4; j++)
        xv[j] = mok ? *(const float4*)(xp + j * 4) : make_float4(0.f, 0.f, 0.f, 0.f);
    cp16(wdst, wsrc0, 16);
    cp16(wdst + 16, wsrc0 + 4, 16);
    cp_commit();

    int gp = lane >> 2, q = lane & 3;
    int arow = wm + (lane & 7) + ((lane >> 3) & 1) * 8;
    int akoff = (lane >> 4) * 8;

#pragma unroll 1
    for (int t = 0; t < 8; t++) {
        int s = t & 1;
#pragma unroll
        for (int j = 0; j < 4; j++) {
            uint2 u;
            u.x = packh2(xv[j].x, xv[j].y);
            u.y = packh2(xv[j].z, xv[j].w);
            *(uint2*)&Xs[s][lm][ks + j * 4] = u;
        }
        __syncthreads();

        if (t < 7) {
            const uint32_t* wsn = wsrc0 + (size_t)(t + 1) * 16 * 128;
            uint32_t wd1 = wdst + ((t + 1) & 1) * WST;
            cp16(wd1, wsn, 16);
            cp16(wd1 + 16, wsn + 4, 16);
            cp_commit();
            asm volatile("cp.async.wait_group 1;" ::: "memory");
            int kn = (t + 1) * 32;
#pragma unroll
            for (int j = 0; j < 4; j++)
                xv[j] = mok ? *(const float4*)(xp + kn + j * 4) : make_float4(0.f, 0.f, 0.f, 0.f);
        } else {
            asm volatile("cp.async.wait_group 0;" ::: "memory");
        }

        uint32_t xbase = (uint32_t)__cvta_generic_to_shared(&Xs[s][0][0]);
#pragma unroll
        for (int ks2 = 0; ks2 < 2; ks2++) {
            int kb = ks2 * 16;
            uint32_t a[4][4], b[4][2];
#pragma unroll
            for (int mt = 0; mt < 4; mt++) {
                uint32_t addr = xbase + (uint32_t)(((arow + mt * 16) * 40 + kb + akoff) * 2);
                ldsm4(a[mt], addr);
            }
#pragma unroll
            for (int nt = 0; nt < 4; nt++) {
                int c = wn + nt * 8 + gp;
                b[nt][0] = Wsp[s][kb / 2 + q][c];
                b[nt][1] = Wsp[s][kb / 2 + q + 4][c];
            }
#pragma unroll
            for (int mt = 0; mt < 4; mt++)
#pragma unroll
                for (int nt = 0; nt < 4; nt++)
                    mma_f16(acc[mt][nt], a[mt], b[nt]);
        }
    }

    int ar = lane >> 2, ac = (lane & 3) * 2;
#pragma unroll
    for (int mt = 0; mt < 4; mt++) {
        int r = m0 + wm + mt * 16 + ar;
#pragma unroll
        for (int nt = 0; nt < 4; nt++) {
            int c = wn + nt * 8 + ac;
            if (r < n)
                *(__half2*)&g_xt1[(size_t)r * 128 + c] =
                    __floats2half2_rn(acc[mt][nt][0], acc[mt][nt][1]);
            if (r + 8 < n)
                *(__half2*)&g_xt1[(size_t)(r + 8) * 128 + c] =
                    __floats2half2_rn(acc[mt][nt][2], acc[mt][nt][3]);
        }
    }

    // ---- fused alar1 epilogue ----
    int hh = wid >> 1;
    float wlv[8], wrv[8];
#pragma unroll
    for (int nt = 0; nt < 4; nt++) {
        int cc = nt * 8 + ac;
        wlv[nt * 2 + 0] = att[hh * 64 + cc];
        wlv[nt * 2 + 1] = att[hh * 64 + cc + 1];
        wrv[nt * 2 + 0] = att[hh * 64 + 32 + cc];
        wrv[nt * 2 + 1] = att[hh * 64 + 32 + cc + 1];
    }
#pragma unroll
    for (int mt = 0; mt < 4; mt++) {
        float alp0 = 0.f, arp0 = 0.f, alp1 = 0.f, arp1 = 0.f;
#pragma unroll
        for (int nt = 0; nt < 4; nt++) {
            alp0 += acc[mt][nt][0] * wlv[nt * 2] + acc[mt][nt][1] * wlv[nt * 2 + 1];
            arp0 += acc[mt][nt][0] * wrv[nt * 2] + acc[mt][nt][1] * wrv[nt * 2 + 1];
            alp1 += acc[mt][nt][2] * wlv[nt * 2] + acc[mt][nt][3] * wlv[nt * 2 + 1];
            arp1 += acc[mt][nt][2] * wrv[nt * 2] + acc[mt][nt][3] * wrv[nt * 2 + 1];
        }
#pragma unroll
        for (int d = 1; d <= 2; d <<= 1) {
            alp0 += __shfl_xor_sync(0xffffffffu, alp0, d);
            arp0 += __shfl_xor_sync(0xffffffffu, arp0, d);
            alp1 += __shfl_xor_sync(0xffffffffu, alp1, d);
            arp1 += __shfl_xor_sync(0xffffffffu, arp1, d);
        }
        if ((lane & 3) == 0) {
            int r = m0 + wm + mt * 16 + ar;
            if (r < n)     { g_al1[r * 4 + hh] = alp0;       g_ar1[r * 4 + hh] = arp0; }
            if (r + 8 < n) { g_al1[(r + 8) * 4 + hh] = alp1; g_ar1[(r + 8) * 4 + hh] = arp1; }
        }
    }
}

// ---------------- agg1: warp/node, occupancy-boosted ----------------
__global__ __launch_bounds__(256, 4) void k_agg1(const float* __restrict__ b1, int n) {
    __shared__ float sw[8][32][4];
    __shared__ int   sr[8][32];
    int w = (blockIdx.x * blockDim.x + threadIdx.x) >> 5;
    if (w >= n) return;
    int lane = threadIdx.x & 31;
    int wz = (threadIdx.x >> 5) & 7;
    int c = w;
    float dc = g_dinv[c];
    float4 alc = *(const float4*)&g_al1[c * 4];
    float4 arc = *(const float4*)&g_ar1[c * 4];
    int beg = g_off[c], end = g_off[c + 1];
    int h = lane >> 3;

    float4 ps = make_float4(0.f, 0.f, 0.f, 0.f);
    float4 acc = make_float4(0.f, 0.f, 0.f, 0.f);

    for (int t0 = beg; t0 < end; t0 += 32) {
        int j = t0 + lane;
        if (j < end) {
            int r = __ldg(&g_adj[j]);
            float4 ar4 = *(const float4*)&g_ar1[r * 4];
            float di = g_dinv[r];
            float e0 = __expf(lrelu(alc.x + ar4.x));
            float e1 = __expf(lrelu(alc.y + ar4.y));
            float e2 = __expf(lrelu(alc.z + ar4.z));
            float e3 = __expf(lrelu(alc.w + ar4.w));
            ps.x += e0; ps.y += e1; ps.z += e2; ps.w += e3;
            *(float4*)&sw[wz][lane][0] = make_float4(di * e0, di * e1, di * e2, di * e3);
            sr[wz][lane] = r;
        }
        __syncwarp();
        int cnt = min(32, end - t0);
#pragma unroll 4
        for (int u = 0; u < cnt; u++) {
            int r = sr[wz][u];
            float wh = sw[wz][u][h];
            uint2 u2 = *(const uint2*)&g_xt1[(size_t)r * 128 + lane * 4];
            float2 f0 = __half22float2(*(__half2*)&u2.x);
            float2 f1 = __half22float2(*(__half2*)&u2.y);
            acc.x += wh * f0.x; acc.y += wh * f0.y;
            acc.z += wh * f1.x; acc.w += wh * f1.y;
        }
        __syncwarp();
    }

#pragma unroll
    for (int d = 16; d > 0; d >>= 1) {
        ps.x += __shfl_xor_sync(0xffffffffu, ps.x, d);
        ps.y += __shfl_xor_sync(0xffffffffu, ps.y, d);
        ps.z += __shfl_xor_sync(0xffffffffu, ps.z, d);
        ps.w += __shfl_xor_sync(0xffffffffu, ps.w, d);
    }
    float se0 = __expf(lrelu(alc.x + arc.x));
    float se1 = __expf(lrelu(alc.y + arc.y));
    float se2 = __expf(lrelu(alc.z + arc.z));
    float se3 = __expf(lrelu(alc.w + arc.w));
    float rs0 = __fdividef(1.0f, ps.x + se0 + 1e-16f);
    float rs1 = __fdividef(1.0f, ps.y + se1 + 1e-16f);
    float rs2 = __fdividef(1.0f, ps.z + se2 + 1e-16f);
    float rs3 = __fdividef(1.0f, ps.w + se3 + 1e-16f);
    float seh = h < 2 ? (h == 0 ? se0 : se1) : (h == 2 ? se2 : se3);
    float rsh = h < 2 ? (h == 0 ? rs0 : rs1) : (h == 2 ? rs2 : rs3);

    uint2 uc = *(const uint2*)&g_xt1[(size_t)c * 128 + lane * 4];
    float2 c0 = __half22float2(*(__half2*)&uc.x);
    float2 c1 = __half22float2(*(__half2*)&uc.y);
    float wself = dc * seh;
    acc.x += wself * c0.x; acc.y += wself * c0.y;
    acc.z += wself * c1.x; acc.w += wself * c1.y;
    float sc = dc * rsh;

    float4 b = *(const float4*)&b1[lane * 4];
    float ox = fmaxf(acc.x * sc + b.x, 0.f);
    float oy = fmaxf(acc.y * sc + b.y, 0.f);
    float oz = fmaxf(acc.z * sc + b.z, 0.f);
    float ow = fmaxf(acc.w * sc + b.w, 0.f);
    uint2 st;
    *(__half2*)&st.x = __floats2half2_rn(ox, oy);
    *(__half2*)&st.y = __floats2half2_rn(oz, ow);
    *(uint2*)&g_h1[(size_t)c * 128 + lane * 4] = st;
}

// ---------------- GEMM2 (fp16 mma, zero-convert H) + fused alar2 epilogue ----------------
__global__ __launch_bounds__(256, 2) void k_gemm2(const float* __restrict__ W2,
                                                  const float* __restrict__ att, int n) {
    __shared__ __align__(16) __half Hs[128][56];
    __shared__ __half Ws2t[16][40];
    int tid = threadIdx.x, lane = tid & 31, wid = tid >> 5;
    int m0 = blockIdx.x * 128;
    int wm = wid * 16;

    float acc[2][4];
#pragma unroll
    for (int nt = 0; nt < 2; nt++)
#pragma unroll
        for (int q = 0; q < 4; q++) acc[nt][q] = 0.f;

    int lm = tid & 127;
    int lkq = (tid >> 7) * 16;
    int wkk = tid >> 3, wc = (tid & 7) * 2;

    for (int k0 = 0; k0 < 128; k0 += 32) {
        uint4 hv0 = make_uint4(0, 0, 0, 0), hv1 = hv0;
        if (m0 + lm < n) {
            const __half* hp = &g_h1[(size_t)(m0 + lm) * 128 + k0 + lkq];
            hv0 = *(const uint4*)hp;
            hv1 = *(const uint4*)(hp + 8);
        }
        *(uint4*)&Hs[lm][lkq] = hv0;
        *(uint4*)&Hs[lm][lkq + 8] = hv1;
        Ws2t[wc][wkk]     = __float2half_rn(W2[(size_t)(k0 + wkk) * 16 + wc]);
        Ws2t[wc + 1][wkk] = __float2half_rn(W2[(size_t)(k0 + wkk) * 16 + wc + 1]);
        __syncthreads();

        int gp = lane >> 2, tq2 = (lane & 3) * 2;
#pragma unroll
        for (int ks = 0; ks < 2; ks++) {
            int kb = ks * 16;
            uint32_t a[4];
            int r = wm + gp;
            a[0] = *(const uint32_t*)&Hs[r][kb + tq2];
            a[1] = *(const uint32_t*)&Hs[r + 8][kb + tq2];
            a[2] = *(const uint32_t*)&Hs[r][kb + tq2 + 8];
            a[3] = *(const uint32_t*)&Hs[r + 8][kb + tq2 + 8];
            uint32_t b0[2], b1[2];
            b0[0] = *(const uint32_t*)&Ws2t[gp][kb + tq2];
            b0[1] = *(const uint32_t*)&Ws2t[gp][kb + tq2 + 8];
            b1[0] = *(const uint32_t*)&Ws2t[8 + gp][kb + tq2];
            b1[1] = *(const uint32_t*)&Ws2t[8 + gp][kb + tq2 + 8];
            mma_f16(acc[0], a, b0);
            mma_f16(acc[1], a, b1);
        }
        __syncthreads();
    }

    int ar = lane >> 2, ac = (lane & 3) * 2;
#pragma unroll
    for (int nt = 0; nt < 2; nt++) {
        int r = m0 + wm + ar;
        int c = nt * 8 + ac;
        if (r < n)
            *(__half2*)&g_xt2[(size_t)r * 16 + c] = __floats2half2_rn(acc[nt][0], acc[nt][1]);
        if (r + 8 < n)
            *(__half2*)&g_xt2[(size_t)(r + 8) * 16 + c] = __floats2half2_rn(acc[nt][2], acc[nt][3]);
    }

    // ---- fused alar2 epilogue ----
    float wlv[4], wrv[4];
#pragma unroll
    for (int nt = 0; nt < 2; nt++) {
        int cc = nt * 8 + ac;
        wlv[nt * 2 + 0] = att[cc];
        wlv[nt * 2 + 1] = att[cc + 1];
        wrv[nt * 2 + 0] = att[16 + cc];
        wrv[nt * 2 + 1] = att[16 + cc + 1];
    }
    float alp0 = 0.f, arp0 = 0.f, alp1 = 0.f, arp1 = 0.f;
#pragma unroll
    for (int nt = 0; nt < 2; nt++) {
        alp0 += acc[nt][0] * wlv[nt * 2] + acc[nt][1] * wlv[nt * 2 + 1];
        arp0 += acc[nt][0] * wrv[nt * 2] + acc[nt][1] * wrv[nt * 2 + 1];
        alp1 += acc[nt][2] * wlv[nt * 2] + acc[nt][3] * wlv[nt * 2 + 1];
        arp1 += acc[nt][2] * wrv[nt * 2] + acc[nt][3] * wrv[nt * 2 + 1];
    }
#pragma unroll
    for (int d = 1; d <= 2; d <<= 1) {
        alp0 += __shfl_xor_sync(0xffffffffu, alp0, d);
        arp0 += __shfl_xor_sync(0xffffffffu, arp0, d);
        alp1 += __shfl_xor_sync(0xffffffffu, alp1, d);
        arp1 += __shfl_xor_sync(0xffffffffu, arp1, d);
    }
    if ((lane & 3) == 0) {
        int r = m0 + wm + ar;
        if (r < n)     { g_al2[r] = alp0;     g_ar2[r] = arp0; }
        if (r + 8 < n) { g_al2[r + 8] = alp1; g_ar2[r + 8] = arp1; }
    }
}

// ---------------- layer2 agg: half-warp per node, occupancy-boosted ----------------
__global__ __launch_bounds__(256, 6) void k_agg2(const float* __restrict__ b2, int n,
                                                 float* __restrict__ out) {
    int hw = (blockIdx.x * blockDim.x + threadIdx.x) >> 4;
    int sub = threadIdx.x & 15;
    unsigned hm = 0xFFFFu << (threadIdx.x & 16);
    bool valid = hw < n;
    int c = valid ? hw : (n - 1);
    float dc = g_dinv[c];
    float alc = g_al2[c];
    int beg = g_off[c], end = g_off[c + 1];

    float ps = 0.f, acc = 0.f;
    for (int t0 = beg; t0 < end; t0 += 16) {
        int j = t0 + sub;
        int r = 0; float wv = 0.f;
        if (j < end) {
            r = __ldg(&g_adj[j]);
            float e = __expf(lrelu(alc + g_ar2[r]));
            ps += e;
            wv = g_dinv[r] * e;
        }
        int cnt = min(16, end - t0);
        for (int u = 0; u < cnt; u++) {
            int ru = __shfl_sync(hm, r, u, 16);
            float wu = __shfl_sync(hm, wv, u, 16);
            acc += wu * __half2float(g_xt2[(size_t)ru * 16 + sub]);
        }
    }
#pragma unroll
    for (int d = 8; d > 0; d >>= 1)
        ps += __shfl_xor_sync(hm, ps, d, 16);
    float se = __expf(lrelu(alc + g_ar2[c]));
    float rs = __fdividef(1.0f, ps + se + 1e-16f);
    acc += dc * se * __half2float(g_xt2[(size_t)c * 16 + sub]);
    if (valid) out[(size_t)c * 16 + sub] = dc * rs * acc + b2[sub];
}

// ---------------- launch (stream-forked; gemm1 at submission index 3 for ncu) ----------------
extern "C" void kernel_launch(void* const* d_in, const int* in_sizes, int n_in,
                              void* d_out, int out_size) {
    const float* x    = (const float*)d_in[0];
    const int*   ei   = (const int*)d_in[1];
    const float* W1   = (const float*)d_in[2];
    const float* att1 = (const float*)d_in[3];
    const float* b1   = (const float*)d_in[4];
    const float* W2   = (const float*)d_in[5];
    const float* att2 = (const float*)d_in[6];
    const float* b2   = (const float*)d_in[7];
    float* out = (float*)d_out;

    int n = in_sizes[0] / 256;
    int e = in_sizes[1] / 2;
    int nb = (n + 1023) / 1024;
    const int T = 256;

    cudaStream_t s2;
    cudaEvent_t evFork, evJoin;
    cudaStreamCreateWithFlags(&s2, cudaStreamNonBlocking);
    cudaEventCreateWithFlags(&evFork, cudaEventDisableTiming);
    cudaEventCreateWithFlags(&evJoin, cudaEventDisableTiming);

    cudaEventRecord(evFork, 0);
    cudaStreamWaitEvent(s2, evFork, 0);

    // chain A (side stream) begins
    k_init<<<(n + T - 1) / T, T, 0, s2>>>(n);                 // idx 0
    k_deg_count<<<(e + T - 1) / T, T, 0, s2>>>(ei, e);        // idx 1
    // main stream: W convert then gemm1 (gemm1 at idx 3 for ncu)
    k_convw<<<64, 256>>>(W1);                                 // idx 2
    k_gemm1<<<(n + 127) / 128, 256>>>(x, att1, n);            // idx 3
    // chain A continues
    k_scan_blocks<<<nb, 1024, 0, s2>>>(n);                    // idx 4
    k_scan_add<<<nb, 1024, 0, s2>>>(n, e);                    // idx 5
    k_scatter<<<(e + T - 1) / T, T, 0, s2>>>(ei, e);          // idx 6
    cudaEventRecord(evJoin, s2);

    // join: aggregation needs both chains
    cudaStreamWaitEvent(0, evJoin, 0);
    k_agg1<<<(n * 32 + 255) / 256, 256>>>(b1, n);

    k_gemm2<<<(n + 127) / 128, 256>>>(W2, att2, n);
    k_agg2<<<(n * 16 + 255) / 256, 256>>>(b2, n, out);
}

// round 17
// speedup vs baseline: 1.1820x; 1.0121x over previous
#include <cuda_runtime.h>
#include <cuda_fp16.h>
#include <math.h>
#include <stdint.h>

#define NN 100000
#define EE 1600000
#define NB_SCAN ((NN + 1023) / 1024)

// ---------------- scratch (static device globals) ----------------
__device__ float    g_deg[NN];
__device__ float    g_dinv[NN];
__device__ __half   g_xt1[(size_t)NN * 128];
__device__ float    g_al1[NN * 4];
__device__ float    g_ar1[NN * 4];
__device__ __half   g_h1[(size_t)NN * 128];
__device__ __half   g_xt2[NN * 16];
__device__ float    g_al2[NN];
__device__ float    g_ar2[NN];
__device__ uint32_t g_w1h[128 * 128];   // W1 pre-paired fp16
// CSR by destination (col)
__device__ int      g_cnt[NN];
__device__ int      g_off[NN + 1];
__device__ int      g_wpos[NN];
__device__ int      g_bsum[NB_SCAN + 1];
__device__ int      g_adj[EE];     // source row only

__device__ __forceinline__ float lrelu(float a) { return a >= 0.f ? a : 0.2f * a; }

__device__ __forceinline__ uint32_t packh2(float x, float y) {
    __half2 h = __floats2half2_rn(x, y);
    return *(uint32_t*)&h;
}

__device__ __forceinline__ void mma_f16(float* c, const uint32_t* a, const uint32_t* b) {
    asm volatile(
        "mma.sync.aligned.m16n8k16.row.col.f32.f16.f16.f32 "
        "{%0,%1,%2,%3}, {%4,%5,%6,%7}, {%8,%9}, {%0,%1,%2,%3};"
        : "+f"(c[0]), "+f"(c[1]), "+f"(c[2]), "+f"(c[3])
        : "r"(a[0]), "r"(a[1]), "r"(a[2]), "r"(a[3]), "r"(b[0]), "r"(b[1]));
}

__device__ __forceinline__ void ldsm4(uint32_t* a, uint32_t addr) {
    asm volatile("ldmatrix.sync.aligned.m8n8.x4.shared.b16 {%0,%1,%2,%3}, [%4];"
                 : "=r"(a[0]), "=r"(a[1]), "=r"(a[2]), "=r"(a[3]) : "r"(addr));
}

__device__ __forceinline__ void cp16(uint32_t d, const void* s, int sz) {
    asm volatile("cp.async.ca.shared.global [%0], [%1], 16, %2;"
                 :: "r"(d), "l"(s), "r"(sz));
}
__device__ __forceinline__ void cp_commit() {
    asm volatile("cp.async.commit_group;" ::: "memory");
}

// ---------------- init ----------------
__global__ void k_init(int n) {
    int i = blockIdx.x * blockDim.x + threadIdx.x;
    if (i < n) { g_deg[i] = 1.0f; g_cnt[i] = 0; }
}

__global__ void k_deg_count(const int* __restrict__ ei, int e) {
    int i = blockIdx.x * blockDim.x + threadIdx.x;
    if (i < e) {
        atomicAdd(&g_deg[ei[i]], 1.0f);
        atomicAdd(&g_cnt[ei[e + i]], 1);
    }
}

// ---------------- W1 -> paired fp16 ----------------
__global__ void k_convw(const float* __restrict__ W) {
    int i = blockIdx.x * blockDim.x + threadIdx.x;
    if (i < 128 * 128) {
        int k2 = i >> 7, nn = i & 127;
        g_w1h[i] = packh2(W[(size_t)(2 * k2) * 128 + nn], W[(size_t)(2 * k2 + 1) * 128 + nn]);
    }
}

// ---------------- multi-block exclusive scan over g_cnt (+ fused dinv) ----------------
__global__ void k_scan_blocks(int n) {
    __shared__ int warpsums[32];
    int i = blockIdx.x * 1024 + threadIdx.x;
    int lane = threadIdx.x & 31, wid = threadIdx.x >> 5;
    if (i < n) g_dinv[i] = rsqrtf(g_deg[i]);
    int v = (i < n) ? g_cnt[i] : 0;
    int s = v;
#pragma unroll
    for (int d = 1; d < 32; d <<= 1) {
        int t = __shfl_up_sync(0xffffffffu, s, d);
        if (lane >= d) s += t;
    }
    if (lane == 31) warpsums[wid] = s;
    __syncthreads();
    if (wid == 0) {
        int ws = warpsums[lane];
#pragma unroll
        for (int d = 1; d < 32; d <<= 1) {
            int t = __shfl_up_sync(0xffffffffu, ws, d);
            if (lane >= d) ws += t;
        }
        warpsums[lane] = ws;
    }
    __syncthreads();
    int base = (wid > 0) ? warpsums[wid - 1] : 0;
    int exc = s - v + base;
    if (i < n) g_off[i] = exc;
    if (threadIdx.x == 1023) g_bsum[blockIdx.x] = exc + v;
}

__global__ void k_scan_add(int n, int e) {
    __shared__ int sbase;
    if (threadIdx.x == 0) sbase = 0;
    __syncthreads();
    if (threadIdx.x < blockIdx.x) atomicAdd(&sbase, g_bsum[threadIdx.x]);
    __syncthreads();
    int i = blockIdx.x * 1024 + threadIdx.x;
    if (i < n) {
        int o = g_off[i] + sbase;
        g_off[i] = o;
        g_wpos[i] = o;
    }
    if (i == 0) g_off[n] = e;
}

__global__ void k_scatter(const int* __restrict__ ei, int e) {
    int i = blockIdx.x * blockDim.x + threadIdx.x;
    if (i >= e) return;
    int r = ei[i], c = ei[e + i];
    int p = atomicAdd(&g_wpos[c], 1);
    g_adj[p] = r;
}

// ---------------- GEMM1: fp16 smem, cp.async W, ldmatrix A, one sync/tile ----------------
__global__ __launch_bounds__(256, 2) void k_gemm1(const float* __restrict__ X,
                                                  const float* __restrict__ att, int n) {
    __shared__ __align__(16) __half   Xs[2][128][40];
    __shared__ __align__(16) uint32_t Wsp[2][16][136];
    int tid = threadIdx.x, lane = tid & 31, wid = tid >> 5;
    int m0 = blockIdx.x * 128;
    int wm = (wid & 1) * 64, wn = (wid >> 1) * 32;

    float acc[4][4][4];
#pragma unroll
    for (int mt = 0; mt < 4; mt++)
#pragma unroll
        for (int nt = 0; nt < 4; nt++)
#pragma unroll
            for (int q = 0; q < 4; q++) acc[mt][nt][q] = 0.f;

    int lm = tid & 127, ks = (tid >> 7) * 16;
    int k2 = tid >> 4, n0 = (tid & 15) * 8;
    bool mok = (m0 + lm < n);
    const float* xp = X + (size_t)(m0 + lm) * 256 + ks;
    const uint32_t* wsrc0 = g_w1h + k2 * 128 + n0;
    uint32_t wdst = (uint32_t)__cvta_generic_to_shared(&Wsp[0][k2][n0]);
    const uint32_t WST = sizeof(uint32_t) * 16 * 136;

    float4 xv[4];
#pragma unroll
    for (int j = 0; j < 4; j++)
        xv[j] = mok ? *(const float4*)(xp + j * 4) : make_float4(0.f, 0.f, 0.f, 0.f);
    cp16(wdst, wsrc0, 16);
    cp16(wdst + 16, wsrc0 + 4, 16);
    cp_commit();

    int gp = lane >> 2, q = lane & 3;
    int arow = wm + (lane & 7) + ((lane >> 3) & 1) * 8;
    int akoff = (lane >> 4) * 8;

#pragma unroll 1
    for (int t = 0; t < 8; t++) {
        int s = t & 1;
#pragma unroll
        for (int j = 0; j < 4; j++) {
            uint2 u;
            u.x = packh2(xv[j].x, xv[j].y);
            u.y = packh2(xv[j].z, xv[j].w);
            *(uint2*)&Xs[s][lm][ks + j * 4] = u;
        }
        __syncthreads();

        if (t < 7) {
            const uint32_t* wsn = wsrc0 + (size_t)(t + 1) * 16 * 128;
            uint32_t wd1 = wdst + ((t + 1) & 1) * WST;
            cp16(wd1, wsn, 16);
            cp16(wd1 + 16, wsn + 4, 16);
            cp_commit();
            asm volatile("cp.async.wait_group 1;" ::: "memory");
            int kn = (t + 1) * 32;
#pragma unroll
            for (int j = 0; j < 4; j++)
                xv[j] = mok ? *(const float4*)(xp + kn + j * 4) : make_float4(0.f, 0.f, 0.f, 0.f);
        } else {
            asm volatile("cp.async.wait_group 0;" ::: "memory");
        }

        uint32_t xbase = (uint32_t)__cvta_generic_to_shared(&Xs[s][0][0]);
#pragma unroll
        for (int ks2 = 0; ks2 < 2; ks2++) {
            int kb = ks2 * 16;
            uint32_t a[4][4], b[4][2];
#pragma unroll
            for (int mt = 0; mt < 4; mt++) {
                uint32_t addr = xbase + (uint32_t)(((arow + mt * 16) * 40 + kb + akoff) * 2);
                ldsm4(a[mt], addr);
            }
#pragma unroll
            for (int nt = 0; nt < 4; nt++) {
                int c = wn + nt * 8 + gp;
                b[nt][0] = Wsp[s][kb / 2 + q][c];
                b[nt][1] = Wsp[s][kb / 2 + q + 4][c];
            }
#pragma unroll
            for (int mt = 0; mt < 4; mt++)
#pragma unroll
                for (int nt = 0; nt < 4; nt++)
                    mma_f16(acc[mt][nt], a[mt], b[nt]);
        }
    }

    int ar = lane >> 2, ac = (lane & 3) * 2;
#pragma unroll
    for (int mt = 0; mt < 4; mt++) {
        int r = m0 + wm + mt * 16 + ar;
#pragma unroll
        for (int nt = 0; nt < 4; nt++) {
            int c = wn + nt * 8 + ac;
            if (r < n)
                *(__half2*)&g_xt1[(size_t)r * 128 + c] =
                    __floats2half2_rn(acc[mt][nt][0], acc[mt][nt][1]);
            if (r + 8 < n)
                *(__half2*)&g_xt1[(size_t)(r + 8) * 128 + c] =
                    __floats2half2_rn(acc[mt][nt][2], acc[mt][nt][3]);
        }
    }

    // ---- fused alar1 epilogue ----
    int hh = wid >> 1;
    float wlv[8], wrv[8];
#pragma unroll
    for (int nt = 0; nt < 4; nt++) {
        int cc = nt * 8 + ac;
        wlv[nt * 2 + 0] = att[hh * 64 + cc];
        wlv[nt * 2 + 1] = att[hh * 64 + cc + 1];
        wrv[nt * 2 + 0] = att[hh * 64 + 32 + cc];
        wrv[nt * 2 + 1] = att[hh * 64 + 32 + cc + 1];
    }
#pragma unroll
    for (int mt = 0; mt < 4; mt++) {
        float alp0 = 0.f, arp0 = 0.f, alp1 = 0.f, arp1 = 0.f;
#pragma unroll
        for (int nt = 0; nt < 4; nt++) {
            alp0 += acc[mt][nt][0] * wlv[nt * 2] + acc[mt][nt][1] * wlv[nt * 2 + 1];
            arp0 += acc[mt][nt][0] * wrv[nt * 2] + acc[mt][nt][1] * wrv[nt * 2 + 1];
            alp1 += acc[mt][nt][2] * wlv[nt * 2] + acc[mt][nt][3] * wlv[nt * 2 + 1];
            arp1 += acc[mt][nt][2] * wrv[nt * 2] + acc[mt][nt][3] * wrv[nt * 2 + 1];
        }
#pragma unroll
        for (int d = 1; d <= 2; d <<= 1) {
            alp0 += __shfl_xor_sync(0xffffffffu, alp0, d);
            arp0 += __shfl_xor_sync(0xffffffffu, arp0, d);
            alp1 += __shfl_xor_sync(0xffffffffu, alp1, d);
            arp1 += __shfl_xor_sync(0xffffffffu, arp1, d);
        }
        if ((lane & 3) == 0) {
            int r = m0 + wm + mt * 16 + ar;
            if (r < n)     { g_al1[r * 4 + hh] = alp0;       g_ar1[r * 4 + hh] = arp0; }
            if (r + 8 < n) { g_al1[(r + 8) * 4 + hh] = alp1; g_ar1[(r + 8) * 4 + hh] = arp1; }
        }
    }
}

// ---------------- agg1: warp/node ----------------
__global__ __launch_bounds__(256, 4) void k_agg1(const float* __restrict__ b1, int n) {
    __shared__ float sw[8][32][4];
    __shared__ int   sr[8][32];
    int w = (blockIdx.x * blockDim.x + threadIdx.x) >> 5;
    if (w >= n) return;
    int lane = threadIdx.x & 31;
    int wz = (threadIdx.x >> 5) & 7;
    int c = w;
    float4 b = *(const float4*)&b1[lane * 4];   // hoisted: overlaps gather latency
    float dc = g_dinv[c];
    float4 alc = *(const float4*)&g_al1[c * 4];
    float4 arc = *(const float4*)&g_ar1[c * 4];
    int beg = g_off[c], end = g_off[c + 1];
    int h = lane >> 3;

    float4 ps = make_float4(0.f, 0.f, 0.f, 0.f);
    float4 acc = make_float4(0.f, 0.f, 0.f, 0.f);

    for (int t0 = beg; t0 < end; t0 += 32) {
        int j = t0 + lane;
        if (j < end) {
            int r = __ldg(&g_adj[j]);
            float4 ar4 = *(const float4*)&g_ar1[r * 4];
            float di = g_dinv[r];
            float e0 = __expf(lrelu(alc.x + ar4.x));
            float e1 = __expf(lrelu(alc.y + ar4.y));
            float e2 = __expf(lrelu(alc.z + ar4.z));
            float e3 = __expf(lrelu(alc.w + ar4.w));
            ps.x += e0; ps.y += e1; ps.z += e2; ps.w += e3;
            *(float4*)&sw[wz][lane][0] = make_float4(di * e0, di * e1, di * e2, di * e3);
            sr[wz][lane] = r;
        }
        __syncwarp();
        int cnt = min(32, end - t0);
#pragma unroll 4
        for (int u = 0; u < cnt; u++) {
            int r = sr[wz][u];
            float wh = sw[wz][u][h];
            uint2 u2 = *(const uint2*)&g_xt1[(size_t)r * 128 + lane * 4];
            float2 f0 = __half22float2(*(__half2*)&u2.x);
            float2 f1 = __half22float2(*(__half2*)&u2.y);
            acc.x += wh * f0.x; acc.y += wh * f0.y;
            acc.z += wh * f1.x; acc.w += wh * f1.y;
        }
        __syncwarp();
    }

#pragma unroll
    for (int d = 16; d > 0; d >>= 1) {
        ps.x += __shfl_xor_sync(0xffffffffu, ps.x, d);
        ps.y += __shfl_xor_sync(0xffffffffu, ps.y, d);
        ps.z += __shfl_xor_sync(0xffffffffu, ps.z, d);
        ps.w += __shfl_xor_sync(0xffffffffu, ps.w, d);
    }
    float se0 = __expf(lrelu(alc.x + arc.x));
    float se1 = __expf(lrelu(alc.y + arc.y));
    float se2 = __expf(lrelu(alc.z + arc.z));
    float se3 = __expf(lrelu(alc.w + arc.w));
    float rs0 = __fdividef(1.0f, ps.x + se0 + 1e-16f);
    float rs1 = __fdividef(1.0f, ps.y + se1 + 1e-16f);
    float rs2 = __fdividef(1.0f, ps.z + se2 + 1e-16f);
    float rs3 = __fdividef(1.0f, ps.w + se3 + 1e-16f);
    float seh = h < 2 ? (h == 0 ? se0 : se1) : (h == 2 ? se2 : se3);
    float rsh = h < 2 ? (h == 0 ? rs0 : rs1) : (h == 2 ? rs2 : rs3);

    uint2 uc = *(const uint2*)&g_xt1[(size_t)c * 128 + lane * 4];
    float2 c0 = __half22float2(*(__half2*)&uc.x);
    float2 c1 = __half22float2(*(__half2*)&uc.y);
    float wself = dc * seh;
    acc.x += wself * c0.x; acc.y += wself * c0.y;
    acc.z += wself * c1.x; acc.w += wself * c1.y;
    float sc = dc * rsh;

    float ox = fmaxf(acc.x * sc + b.x, 0.f);
    float oy = fmaxf(acc.y * sc + b.y, 0.f);
    float oz = fmaxf(acc.z * sc + b.z, 0.f);
    float ow = fmaxf(acc.w * sc + b.w, 0.f);
    uint2 st;
    *(__half2*)&st.x = __floats2half2_rn(ox, oy);
    *(__half2*)&st.y = __floats2half2_rn(oz, ow);
    *(uint2*)&g_h1[(size_t)c * 128 + lane * 4] = st;
}

// ---------------- GEMM2 (fp16 mma) + fused alar2 epilogue, occupancy-boosted ----------------
__global__ __launch_bounds__(256, 4) void k_gemm2(const float* __restrict__ W2,
                                                  const float* __restrict__ att, int n) {
    __shared__ __align__(16) __half Hs[128][56];
    __shared__ __half Ws2t[16][40];
    int tid = threadIdx.x, lane = tid & 31, wid = tid >> 5;
    int m0 = blockIdx.x * 128;
    int wm = wid * 16;

    float acc[2][4];
#pragma unroll
    for (int nt = 0; nt < 2; nt++)
#pragma unroll
        for (int q = 0; q < 4; q++) acc[nt][q] = 0.f;

    int lm = tid & 127;
    int lkq = (tid >> 7) * 16;
    int wkk = tid >> 3, wc = (tid & 7) * 2;

    for (int k0 = 0; k0 < 128; k0 += 32) {
        uint4 hv0 = make_uint4(0, 0, 0, 0), hv1 = hv0;
        if (m0 + lm < n) {
            const __half* hp = &g_h1[(size_t)(m0 + lm) * 128 + k0 + lkq];
            hv0 = *(const uint4*)hp;
            hv1 = *(const uint4*)(hp + 8);
        }
        *(uint4*)&Hs[lm][lkq] = hv0;
        *(uint4*)&Hs[lm][lkq + 8] = hv1;
        Ws2t[wc][wkk]     = __float2half_rn(W2[(size_t)(k0 + wkk) * 16 + wc]);
        Ws2t[wc + 1][wkk] = __float2half_rn(W2[(size_t)(k0 + wkk) * 16 + wc + 1]);
        __syncthreads();

        int gp = lane >> 2, tq2 = (lane & 3) * 2;
#pragma unroll
        for (int ks = 0; ks < 2; ks++) {
            int kb = ks * 16;
            uint32_t a[4];
            int r = wm + gp;
            a[0] = *(const uint32_t*)&Hs[r][kb + tq2];
            a[1] = *(const uint32_t*)&Hs[r + 8][kb + tq2];
            a[2] = *(const uint32_t*)&Hs[r][kb + tq2 + 8];
            a[3] = *(const uint32_t*)&Hs[r + 8][kb + tq2 + 8];
            uint32_t b0[2], b1[2];
            b0[0] = *(const uint32_t*)&Ws2t[gp][kb + tq2];
            b0[1] = *(const uint32_t*)&Ws2t[gp][kb + tq2 + 8];
            b1[0] = *(const uint32_t*)&Ws2t[8 + gp][kb + tq2];
            b1[1] = *(const uint32_t*)&Ws2t[8 + gp][kb + tq2 + 8];
            mma_f16(acc[0], a, b0);
            mma_f16(acc[1], a, b1);
        }
        __syncthreads();
    }

    int ar = lane >> 2, ac = (lane & 3) * 2;
#pragma unroll
    for (int nt = 0; nt < 2; nt++) {
        int r = m0 + wm + ar;
        int c = nt * 8 + ac;
        if (r < n)
            *(__half2*)&g_xt2[(size_t)r * 16 + c] = __floats2half2_rn(acc[nt][0], acc[nt][1]);
        if (r + 8 < n)
            *(__half2*)&g_xt2[(size_t)(r + 8) * 16 + c] = __floats2half2_rn(acc[nt][2], acc[nt][3]);
    }

    // ---- fused alar2 epilogue ----
    float wlv[4], wrv[4];
#pragma unroll
    for (int nt = 0; nt < 2; nt++) {
        int cc = nt * 8 + ac;
        wlv[nt * 2 + 0] = att[cc];
        wlv[nt * 2 + 1] = att[cc + 1];
        wrv[nt * 2 + 0] = att[16 + cc];
        wrv[nt * 2 + 1] = att[16 + cc + 1];
    }
    float alp0 = 0.f, arp0 = 0.f, alp1 = 0.f, arp1 = 0.f;
#pragma unroll
    for (int nt = 0; nt < 2; nt++) {
        alp0 += acc[nt][0] * wlv[nt * 2] + acc[nt][1] * wlv[nt * 2 + 1];
        arp0 += acc[nt][0] * wrv[nt * 2] + acc[nt][1] * wrv[nt * 2 + 1];
        alp1 += acc[nt][2] * wlv[nt * 2] + acc[nt][3] * wlv[nt * 2 + 1];
        arp1 += acc[nt][2] * wrv[nt * 2] + acc[nt][3] * wrv[nt * 2 + 1];
    }
#pragma unroll
    for (int d = 1; d <= 2; d <<= 1) {
        alp0 += __shfl_xor_sync(0xffffffffu, alp0, d);
        arp0 += __shfl_xor_sync(0xffffffffu, arp0, d);
        alp1 += __shfl_xor_sync(0xffffffffu, alp1, d);
        arp1 += __shfl_xor_sync(0xffffffffu, arp1, d);
    }
    if ((lane & 3) == 0) {
        int r = m0 + wm + ar;
        if (r < n)     { g_al2[r] = alp0;     g_ar2[r] = arp0; }
        if (r + 8 < n) { g_al2[r + 8] = alp1; g_ar2[r + 8] = arp1; }
    }
}

// ---------------- layer2 agg: half-warp per node ----------------
__global__ __launch_bounds__(256, 6) void k_agg2(const float* __restrict__ b2, int n,
                                                 float* __restrict__ out) {
    int hw = (blockIdx.x * blockDim.x + threadIdx.x) >> 4;
    int sub = threadIdx.x & 15;
    unsigned hm = 0xFFFFu << (threadIdx.x & 16);
    bool valid = hw < n;
    int c = valid ? hw : (n - 1);
    float dc = g_dinv[c];
    float alc = g_al2[c];
    int beg = g_off[c], end = g_off[c + 1];

    float ps = 0.f, acc = 0.f;
    for (int t0 = beg; t0 < end; t0 += 16) {
        int j = t0 + sub;
        int r = 0; float wv = 0.f;
        if (j < end) {
            r = __ldg(&g_adj[j]);
            float e = __expf(lrelu(alc + g_ar2[r]));
            ps += e;
            wv = g_dinv[r] * e;
        }
        int cnt = min(16, end - t0);
        for (int u = 0; u < cnt; u++) {
            int ru = __shfl_sync(hm, r, u, 16);
            float wu = __shfl_sync(hm, wv, u, 16);
            acc += wu * __half2float(g_xt2[(size_t)ru * 16 + sub]);
        }
    }
#pragma unroll
    for (int d = 8; d > 0; d >>= 1)
        ps += __shfl_xor_sync(hm, ps, d, 16);
    float se = __expf(lrelu(alc + g_ar2[c]));
    float rs = __fdividef(1.0f, ps + se + 1e-16f);
    acc += dc * se * __half2float(g_xt2[(size_t)c * 16 + sub]);
    if (valid) out[(size_t)c * 16 + sub] = dc * rs * acc + b2[sub];
}

// ---------------- launch (stream-forked; convw off critical path) ----------------
extern "C" void kernel_launch(void* const* d_in, const int* in_sizes, int n_in,
                              void* d_out, int out_size) {
    const float* x    = (const float*)d_in[0];
    const int*   ei   = (const int*)d_in[1];
    const float* W1   = (const float*)d_in[2];
    const float* att1 = (const float*)d_in[3];
    const float* b1   = (const float*)d_in[4];
    const float* W2   = (const float*)d_in[5];
    const float* att2 = (const float*)d_in[6];
    const float* b2   = (const float*)d_in[7];
    float* out = (float*)d_out;

    int n = in_sizes[0] / 256;
    int e = in_sizes[1] / 2;
    int nb = (n + 1023) / 1024;
    const int T = 256;

    cudaStream_t s2;
    cudaEvent_t evFork, evW, evJoin;
    cudaStreamCreateWithFlags(&s2, cudaStreamNonBlocking);
    cudaEventCreateWithFlags(&evFork, cudaEventDisableTiming);
    cudaEventCreateWithFlags(&evW, cudaEventDisableTiming);
    cudaEventCreateWithFlags(&evJoin, cudaEventDisableTiming);

    cudaEventRecord(evFork, 0);
    cudaStreamWaitEvent(s2, evFork, 0);

    // side stream: W convert first (gemm1 waits on it), then CSR chain
    k_convw<<<64, 256, 0, s2>>>(W1);                          // idx 0
    cudaEventRecord(evW, s2);
    k_init<<<(n + T - 1) / T, T, 0, s2>>>(n);                 // idx 1
    k_deg_count<<<(e + T - 1) / T, T, 0, s2>>>(ei, e);        // idx 2
    // main stream: gemm1 (idx 3 — profiled), waits only on convw
    cudaStreamWaitEvent(0, evW, 0);
    k_gemm1<<<(n + 127) / 128, 256>>>(x, att1, n);            // idx 3
    // side stream continues
    k_scan_blocks<<<nb, 1024, 0, s2>>>(n);                    // idx 4
    k_scan_add<<<nb, 1024, 0, s2>>>(n, e);                    // idx 5
    k_scatter<<<(e + T - 1) / T, T, 0, s2>>>(ei, e);          // idx 6
    cudaEventRecord(evJoin, s2);

    // join: aggregation needs both chains
    cudaStreamWaitEvent(0, evJoin, 0);
    k_agg1<<<(n * 32 + 255) / 256, 256>>>(b1, n);

    k_gemm2<<<(n + 127) / 128, 256>>>(W2, att2, n);
    k_agg2<<<(n * 16 + 255) / 256, 256>>>(b2, n, out);
}